// round 1
// baseline (speedup 1.0000x reference)
#include <cuda_runtime.h>

#define B_  4
#define S_  2048
#define D_  1024
#define H_  16
#define DK_ 64
#define M_  (B_*S_)   // 8192

// Scratch (device-global: no allocations allowed)
__device__ float g_Q[B_*H_*S_*DK_];
__device__ float g_K[B_*H_*S_*DK_];
__device__ float g_V[B_*H_*S_*DK_];
__device__ float g_O[B_*H_*S_*DK_];

#define BM 128
#define BN 128
#define BK 16

// ---------------------------------------------------------------------------
// Kernel 1: fused QKV projection.
// C[8192 x 1024] = X[8192 x 1024] @ Wcat, where Wcat[d][h*64+k] = W[h][d][k].
// Output written directly in [B][H][S][Dk] layout for the attention kernel.
// blockIdx.z selects Q/K/V.
// ---------------------------------------------------------------------------
__global__ __launch_bounds__(256) void qkv_kernel(
    const float* __restrict__ X,
    const float* __restrict__ WQ,
    const float* __restrict__ WK,
    const float* __restrict__ WV)
{
    __shared__ float As[BK][BM + 4];   // A transposed (k-major), +4 pad for stores
    __shared__ float Bs[BK][BN];

    const float* W = (blockIdx.z == 0) ? WQ : (blockIdx.z == 1) ? WK : WV;
    float* Out     = (blockIdx.z == 0) ? g_Q : (blockIdx.z == 1) ? g_K : g_V;

    const int tid = threadIdx.x;
    const int m0 = blockIdx.y * BM;
    const int n0 = blockIdx.x * BN;
    const int tm = (tid >> 4) << 3;   // 16 thread-rows * 8
    const int tn = (tid & 15) << 3;   // 16 thread-cols * 8

    float acc[8][8];
#pragma unroll
    for (int i = 0; i < 8; i++)
#pragma unroll
        for (int j = 0; j < 8; j++) acc[i][j] = 0.f;

    const int arow = tid >> 2, ac4 = tid & 3;    // A: 64 rows/pass, 4 float4 cols
    const int brow = tid >> 5, bc4 = tid & 31;   // B: 8 k-rows/pass, 32 float4 cols

    for (int k0 = 0; k0 < D_; k0 += BK) {
        // ---- load A tile (X), store transposed ----
#pragma unroll
        for (int p = 0; p < 2; p++) {
            int rr = arow + p * 64;
            float4 v = *(const float4*)&X[(size_t)(m0 + rr) * D_ + k0 + ac4 * 4];
            As[ac4 * 4 + 0][rr] = v.x;
            As[ac4 * 4 + 1][rr] = v.y;
            As[ac4 * 4 + 2][rr] = v.z;
            As[ac4 * 4 + 3][rr] = v.w;
        }
        // ---- load B tile (stacked per-head weights) ----
#pragma unroll
        for (int p = 0; p < 2; p++) {
            int kk = brow + p * 8;
            int n  = n0 + bc4 * 4;          // 4 consecutive n within one head block
            int d  = k0 + kk;
            const float4 v = *(const float4*)&W[((size_t)(n >> 6) * D_ + d) * DK_ + (n & 63)];
            *(float4*)&Bs[kk][bc4 * 4] = v;
        }
        __syncthreads();

#pragma unroll
        for (int kk = 0; kk < BK; kk++) {
            float a[8], b[8];
            *(float4*)&a[0] = *(float4*)&As[kk][tm];
            *(float4*)&a[4] = *(float4*)&As[kk][tm + 4];
            *(float4*)&b[0] = *(float4*)&Bs[kk][tn];
            *(float4*)&b[4] = *(float4*)&Bs[kk][tn + 4];
#pragma unroll
            for (int i = 0; i < 8; i++)
#pragma unroll
                for (int j = 0; j < 8; j++) acc[i][j] += a[i] * b[j];
        }
        __syncthreads();
    }

    // Epilogue: write into [B][H][S][Dk] layout. tn block of 8 stays in one head.
    const int n = n0 + tn;
    const int h = n >> 6;
    const int kkb = n & 63;
#pragma unroll
    for (int i = 0; i < 8; i++) {
        int m = m0 + tm + i;
        int b = m >> 11;
        int s = m & (S_ - 1);
        float* dst = &Out[(((size_t)b * H_ + h) * S_ + s) * DK_ + kkb];
        float4 v0 = make_float4(acc[i][0], acc[i][1], acc[i][2], acc[i][3]);
        float4 v1 = make_float4(acc[i][4], acc[i][5], acc[i][6], acc[i][7]);
        *(float4*)&dst[0] = v0;
        *(float4*)&dst[4] = v1;
    }
}

// ---------------------------------------------------------------------------
// Kernel 2: flash-style attention, fp32, online softmax.
// Grid: (S/64 q-tiles, B*H). Block: 256 threads = 64 rows x 4 col-groups.
// Smem rows stride 68 floats => bank-conflict-free LDS.128 under the
// interleaved column mapping (score col c = g + 4*i, o col d = 16*jj + 4*g).
// ---------------------------------------------------------------------------
#define LDA 68
#define ATTN_SMEM (3 * 64 * LDA * 4)

__global__ __launch_bounds__(256) void attn_kernel() {
    extern __shared__ float sm[];
    float* qs = sm;                 // [64][LDA]
    float* ks = sm + 64 * LDA;      // [64][LDA], reused as ps after scores
    float* vs = sm + 2 * 64 * LDA;  // [64][LDA]

    const int tid = threadIdx.x;
    const int r = tid >> 2;         // q row 0..63
    const int g = tid & 3;          // col group 0..3
    const int bh = blockIdx.y;
    const int q0 = blockIdx.x * 64;
    const float scale = 0.125f;     // 1/sqrt(64)
    const size_t base = (size_t)bh * S_ * DK_;

    // load q tile, fold in softmax scale
    {
        int row = tid >> 4;
        int c4 = (tid & 15) * 4;
#pragma unroll
        for (int p = 0; p < 4; p++) {
            int rr = row + p * 16;
            float4 v = *(const float4*)&g_Q[base + (size_t)(q0 + rr) * DK_ + c4];
            v.x *= scale; v.y *= scale; v.z *= scale; v.w *= scale;
            *(float4*)&qs[rr * LDA + c4] = v;
        }
    }

    float oacc[16];
#pragma unroll
    for (int i = 0; i < 16; i++) oacc[i] = 0.f;
    float mrow = -1e30f, lrow = 0.f;

    for (int j0 = 0; j0 < S_; j0 += 64) {
        __syncthreads();   // previous iteration done reading ps/vs
        // load K, V tiles
        {
            int row = tid >> 4;
            int c4 = (tid & 15) * 4;
#pragma unroll
            for (int p = 0; p < 4; p++) {
                int rr = row + p * 16;
                *(float4*)&ks[rr * LDA + c4] =
                    *(const float4*)&g_K[base + (size_t)(j0 + rr) * DK_ + c4];
                *(float4*)&vs[rr * LDA + c4] =
                    *(const float4*)&g_V[base + (size_t)(j0 + rr) * DK_ + c4];
            }
        }
        __syncthreads();

        // scores: thread owns kv cols c = g + 4*i  (bank-spread across g)
        float sc[16];
#pragma unroll
        for (int i = 0; i < 16; i++) sc[i] = 0.f;
        for (int d = 0; d < DK_; d += 4) {
            float4 qv = *(float4*)&qs[r * LDA + d];
#pragma unroll
            for (int i = 0; i < 16; i++) {
                float4 kv = *(float4*)&ks[(g + 4 * i) * LDA + d];
                sc[i] += qv.x * kv.x + qv.y * kv.y + qv.z * kv.z + qv.w * kv.w;
            }
        }

        // online softmax update
        float tmax = sc[0];
#pragma unroll
        for (int i = 1; i < 16; i++) tmax = fmaxf(tmax, sc[i]);
        tmax = fmaxf(tmax, __shfl_xor_sync(0xffffffffu, tmax, 1));
        tmax = fmaxf(tmax, __shfl_xor_sync(0xffffffffu, tmax, 2));
        float mnew = fmaxf(mrow, tmax);
        float corr = __expf(mrow - mnew);
        float psum = 0.f;
#pragma unroll
        for (int i = 0; i < 16; i++) {
            sc[i] = __expf(sc[i] - mnew);
            psum += sc[i];
        }
        psum += __shfl_xor_sync(0xffffffffu, psum, 1);
        psum += __shfl_xor_sync(0xffffffffu, psum, 2);
        lrow = lrow * corr + psum;
        mrow = mnew;
#pragma unroll
        for (int i = 0; i < 16; i++) oacc[i] *= corr;

        __syncthreads();   // everyone done reading ks before overwrite with p
        float* ps = ks;
#pragma unroll
        for (int i = 0; i < 16; i++) ps[r * LDA + g + 4 * i] = sc[i];
        __syncthreads();

        // o update: thread owns d cols = 16*jj + 4*g .. +3 (bank-spread over g)
        for (int c = 0; c < 64; c++) {
            float pv = ps[r * LDA + c];
#pragma unroll
            for (int jj = 0; jj < 4; jj++) {
                float4 vv = *(float4*)&vs[c * LDA + jj * 16 + 4 * g];
                oacc[jj * 4 + 0] += pv * vv.x;
                oacc[jj * 4 + 1] += pv * vv.y;
                oacc[jj * 4 + 2] += pv * vv.z;
                oacc[jj * 4 + 3] += pv * vv.w;
            }
        }
    }

    const float inv = 1.f / lrow;
#pragma unroll
    for (int jj = 0; jj < 4; jj++) {
        float4 v = make_float4(oacc[jj * 4 + 0] * inv, oacc[jj * 4 + 1] * inv,
                               oacc[jj * 4 + 2] * inv, oacc[jj * 4 + 3] * inv);
        *(float4*)&g_O[base + (size_t)(q0 + r) * DK_ + jj * 16 + 4 * g] = v;
    }
}

// ---------------------------------------------------------------------------
// Kernel 3: output projection.
// out[8192 x 1024] = Ocat[8192 x 1024] @ WO, Ocat[m][c] = g_O[b][c/64][s][c%64].
// ---------------------------------------------------------------------------
__global__ __launch_bounds__(256) void out_kernel(
    const float* __restrict__ WO, float* __restrict__ Out)
{
    __shared__ float As[BK][BM + 4];
    __shared__ float Bs[BK][BN];

    const int tid = threadIdx.x;
    const int m0 = blockIdx.y * BM;
    const int n0 = blockIdx.x * BN;
    const int tm = (tid >> 4) << 3;
    const int tn = (tid & 15) << 3;

    float acc[8][8];
#pragma unroll
    for (int i = 0; i < 8; i++)
#pragma unroll
        for (int j = 0; j < 8; j++) acc[i][j] = 0.f;

    const int arow = tid >> 2, ac4 = tid & 3;
    const int brow = tid >> 5, bc4 = tid & 31;

    for (int k0 = 0; k0 < D_; k0 += BK) {
#pragma unroll
        for (int p = 0; p < 2; p++) {
            int rr = arow + p * 64;
            int m = m0 + rr;
            int b = m >> 11;
            int s = m & (S_ - 1);
            int k = k0 + ac4 * 4;   // 4 consecutive c within one head block
            float4 v = *(const float4*)
                &g_O[(((size_t)b * H_ + (k >> 6)) * S_ + s) * DK_ + (k & 63)];
            As[ac4 * 4 + 0][rr] = v.x;
            As[ac4 * 4 + 1][rr] = v.y;
            As[ac4 * 4 + 2][rr] = v.z;
            As[ac4 * 4 + 3][rr] = v.w;
        }
#pragma unroll
        for (int p = 0; p < 2; p++) {
            int kk = brow + p * 8;
            *(float4*)&Bs[kk][bc4 * 4] =
                *(const float4*)&WO[(size_t)(k0 + kk) * D_ + n0 + bc4 * 4];
        }
        __syncthreads();

#pragma unroll
        for (int kk = 0; kk < BK; kk++) {
            float a[8], b[8];
            *(float4*)&a[0] = *(float4*)&As[kk][tm];
            *(float4*)&a[4] = *(float4*)&As[kk][tm + 4];
            *(float4*)&b[0] = *(float4*)&Bs[kk][tn];
            *(float4*)&b[4] = *(float4*)&Bs[kk][tn + 4];
#pragma unroll
            for (int i = 0; i < 8; i++)
#pragma unroll
                for (int j = 0; j < 8; j++) acc[i][j] += a[i] * b[j];
        }
        __syncthreads();
    }

#pragma unroll
    for (int i = 0; i < 8; i++) {
        int m = m0 + tm + i;
        float4 v0 = make_float4(acc[i][0], acc[i][1], acc[i][2], acc[i][3]);
        float4 v1 = make_float4(acc[i][4], acc[i][5], acc[i][6], acc[i][7]);
        *(float4*)&Out[(size_t)m * D_ + n0 + tn]     = v0;
        *(float4*)&Out[(size_t)m * D_ + n0 + tn + 4] = v1;
    }
}

// ---------------------------------------------------------------------------
extern "C" void kernel_launch(void* const* d_in, const int* in_sizes, int n_in,
                              void* d_out, int out_size)
{
    const float* x  = (const float*)d_in[0];
    const float* WQ = (const float*)d_in[1];
    const float* WK = (const float*)d_in[2];
    const float* WV = (const float*)d_in[3];
    const float* WO = (const float*)d_in[4];
    float* out = (float*)d_out;

    (void)in_sizes; (void)n_in; (void)out_size;

    // 1) QKV projections: grid (N/BN, M/BM, 3)
    qkv_kernel<<<dim3(D_ / BN, M_ / BM, 3), 256>>>(x, WQ, WK, WV);

    // 2) attention: grid (S/64 q-tiles, B*H); 52224 B dynamic smem (> 48KB)
    cudaFuncSetAttribute(attn_kernel,
                         cudaFuncAttributeMaxDynamicSharedMemorySize, ATTN_SMEM);
    attn_kernel<<<dim3(S_ / 64, B_ * H_), 256, ATTN_SMEM>>>();

    // 3) output projection
    out_kernel<<<dim3(D_ / BN, M_ / BM), 256>>>(WO, out);
}

// round 2
// speedup vs baseline: 1.8067x; 1.8067x over previous
#include <cuda_runtime.h>

#define B_  4
#define S_  2048
#define D_  1024
#define H_  16
#define DK_ 64
#define M_  (B_*S_)   // 8192

typedef unsigned long long ull;

// Scratch (device-global: no allocations allowed)
__device__ float g_Q[B_*H_*S_*DK_];
__device__ float g_K[B_*H_*S_*DK_];
__device__ float g_V[B_*H_*S_*DK_];
__device__ float g_O[B_*H_*S_*DK_];

// ---------------------------------------------------------------------------
// f32x2 packed-math helpers (sm_100+ PTX; SASS FFMA2 path ptxas won't emit)
// ---------------------------------------------------------------------------
__device__ __forceinline__ void fma2(ull& d, ull a, ull b) {
    asm("fma.rn.f32x2 %0, %1, %2, %0;" : "+l"(d) : "l"(a), "l"(b));
}
__device__ __forceinline__ ull dup2(float x) {
    ull r; asm("mov.b64 %0, {%1, %1};" : "=l"(r) : "f"(x)); return r;
}
__device__ __forceinline__ void mul2ip(ull& d, ull a) {
    asm("mul.rn.f32x2 %0, %0, %1;" : "+l"(d) : "l"(a));
}
__device__ __forceinline__ float2 unp(ull v) {
    float2 r; asm("mov.b64 {%0, %1}, %2;" : "=f"(r.x), "=f"(r.y) : "l"(v)); return r;
}

#define BM 128
#define BN 128
#define BK 16

// ---------------------------------------------------------------------------
// Kernel 1: fused QKV projection (FFMA2 microkernel).
// C[8192 x 1024] = X @ Wcat; output written in [B][H][S][Dk] layout.
// ---------------------------------------------------------------------------
__global__ __launch_bounds__(256) void qkv_kernel(
    const float* __restrict__ X,
    const float* __restrict__ WQ,
    const float* __restrict__ WK,
    const float* __restrict__ WV)
{
    __shared__ __align__(16) float As[BK][BM + 4];
    __shared__ __align__(16) float Bs[BK][BN];

    const float* W = (blockIdx.z == 0) ? WQ : (blockIdx.z == 1) ? WK : WV;
    float* Out     = (blockIdx.z == 0) ? g_Q : (blockIdx.z == 1) ? g_K : g_V;

    const int tid = threadIdx.x;
    const int m0 = blockIdx.y * BM;
    const int n0 = blockIdx.x * BN;
    const int tm = (tid >> 4) << 3;
    const int tn = (tid & 15) << 3;

    ull acc2[8][4];
#pragma unroll
    for (int i = 0; i < 8; i++)
#pragma unroll
        for (int j = 0; j < 4; j++) acc2[i][j] = 0ull;

    const int arow = tid >> 2, ac4 = tid & 3;
    const int brow = tid >> 5, bc4 = tid & 31;

    for (int k0 = 0; k0 < D_; k0 += BK) {
#pragma unroll
        for (int p = 0; p < 2; p++) {
            int rr = arow + p * 64;
            float4 v = *(const float4*)&X[(size_t)(m0 + rr) * D_ + k0 + ac4 * 4];
            As[ac4 * 4 + 0][rr] = v.x;
            As[ac4 * 4 + 1][rr] = v.y;
            As[ac4 * 4 + 2][rr] = v.z;
            As[ac4 * 4 + 3][rr] = v.w;
        }
#pragma unroll
        for (int p = 0; p < 2; p++) {
            int kk = brow + p * 8;
            int n  = n0 + bc4 * 4;
            int d  = k0 + kk;
            const float4 v = *(const float4*)&W[((size_t)(n >> 6) * D_ + d) * DK_ + (n & 63)];
            *(float4*)&Bs[kk][bc4 * 4] = v;
        }
        __syncthreads();

#pragma unroll
        for (int kk = 0; kk < BK; kk++) {
            float a[8];
            *(float4*)&a[0] = *(float4*)&As[kk][tm];
            *(float4*)&a[4] = *(float4*)&As[kk][tm + 4];
            ulonglong2 b0 = *(ulonglong2*)&Bs[kk][tn];
            ulonglong2 b1 = *(ulonglong2*)&Bs[kk][tn + 4];
            ull bp[4] = {b0.x, b0.y, b1.x, b1.y};
#pragma unroll
            for (int i = 0; i < 8; i++) {
                ull ad = dup2(a[i]);
#pragma unroll
                for (int j = 0; j < 4; j++) fma2(acc2[i][j], ad, bp[j]);
            }
        }
        __syncthreads();
    }

    const int n = n0 + tn;
    const int h = n >> 6;
    const int kkb = n & 63;
#pragma unroll
    for (int i = 0; i < 8; i++) {
        int m = m0 + tm + i;
        int b = m >> 11;
        int s = m & (S_ - 1);
        float* dst = &Out[(((size_t)b * H_ + h) * S_ + s) * DK_ + kkb];
        *(ulonglong2*)&dst[0] = make_ulonglong2(acc2[i][0], acc2[i][1]);
        *(ulonglong2*)&dst[4] = make_ulonglong2(acc2[i][2], acc2[i][3]);
    }
}

// ---------------------------------------------------------------------------
// Kernel 2: flash attention, fp32 + FFMA2, 128x128 tiles, 8x8 scores/thread.
// 256 threads as 16(ty: 8-row groups) x 16(tx).
// Score cols per thread: c = tx + 16*j (bank-spread scalar K reads).
// ---------------------------------------------------------------------------
#define QS_LD 132
#define KS_LD 68
#define PS_LD 132
#define QS_FLOATS (64 * QS_LD)
#define KS_FLOATS (128 * KS_LD)
#define ATTN_SMEM ((QS_FLOATS + 2 * KS_FLOATS + 128 * PS_LD) * 4)

__global__ __launch_bounds__(256) void attn_kernel() {
    extern __shared__ __align__(16) float sm[];
    float* qsT = sm;                       // [64][132]  d-major Q
    float* ks  = sm + QS_FLOATS;           // [128][68]  row-major K
    float* vs  = ks + KS_FLOATS;           // [128][68]  row-major V
    float* psT = vs + KS_FLOATS;           // [128][132] c-major P

    const int tid = threadIdx.x;
    const int tx = tid & 15;
    const int ty = tid >> 4;
    const int r0 = ty * 8;                 // 8 q-rows
    const int d0 = tx * 4;                 // 4 output d-cols
    const int bh = blockIdx.y;
    const int q0 = blockIdx.x * 128;
    const size_t base = (size_t)bh * S_ * DK_;

    // load + transpose Q (softmax scale folded)
    for (int i = tid; i < 128 * 16; i += 256) {
        int rr = i >> 4, c4 = (i & 15) * 4;
        float4 v = *(const float4*)&g_Q[base + (size_t)(q0 + rr) * DK_ + c4];
        qsT[(c4 + 0) * QS_LD + rr] = v.x * 0.125f;
        qsT[(c4 + 1) * QS_LD + rr] = v.y * 0.125f;
        qsT[(c4 + 2) * QS_LD + rr] = v.z * 0.125f;
        qsT[(c4 + 3) * QS_LD + rr] = v.w * 0.125f;
    }

    ull oacc[8][2];
#pragma unroll
    for (int i = 0; i < 8; i++) { oacc[i][0] = 0ull; oacc[i][1] = 0ull; }
    float mrow[8], lrow[8];
#pragma unroll
    for (int i = 0; i < 8; i++) { mrow[i] = -1e30f; lrow[i] = 0.f; }

    const float* kp[8];
#pragma unroll
    for (int j = 0; j < 8; j++) kp[j] = &ks[(tx + 16 * j) * KS_LD];

    for (int j0 = 0; j0 < S_; j0 += 128) {
        __syncthreads();   // prev PV done with vs/psT
        for (int i = tid; i < 128 * 16; i += 256) {
            int c = i >> 4, c4 = (i & 15) * 4;
            *(float4*)&ks[c * KS_LD + c4] =
                *(const float4*)&g_K[base + (size_t)(j0 + c) * DK_ + c4];
            *(float4*)&vs[c * KS_LD + c4] =
                *(const float4*)&g_V[base + (size_t)(j0 + c) * DK_ + c4];
        }
        __syncthreads();

        // ---- scores: sc2[row-pair][col j], rank-1 over d ----
        ull sc2[4][8];
#pragma unroll
        for (int ip = 0; ip < 4; ip++)
#pragma unroll
            for (int j = 0; j < 8; j++) sc2[ip][j] = 0ull;

#pragma unroll 4
        for (int d = 0; d < 64; d++) {
            ulonglong2 qa = *(ulonglong2*)&qsT[d * QS_LD + r0];
            ulonglong2 qb = *(ulonglong2*)&qsT[d * QS_LD + r0 + 4];
            ull q2[4] = {qa.x, qa.y, qb.x, qb.y};
#pragma unroll
            for (int j = 0; j < 8; j++) {
                ull kd = dup2(kp[j][d]);
                fma2(sc2[0][j], q2[0], kd);
                fma2(sc2[1][j], q2[1], kd);
                fma2(sc2[2][j], q2[2], kd);
                fma2(sc2[3][j], q2[3], kd);
            }
        }

        // unpack scores
        float s[8][8];
#pragma unroll
        for (int ip = 0; ip < 4; ip++)
#pragma unroll
            for (int j = 0; j < 8; j++) {
                float2 t = unp(sc2[ip][j]);
                s[2 * ip + 0][j] = t.x;
                s[2 * ip + 1][j] = t.y;
            }

        // ---- online softmax (row stats across tx lanes) ----
#pragma unroll
        for (int i = 0; i < 8; i++) {
            float tmax = s[i][0];
#pragma unroll
            for (int j = 1; j < 8; j++) tmax = fmaxf(tmax, s[i][j]);
            tmax = fmaxf(tmax, __shfl_xor_sync(0xffffffffu, tmax, 1));
            tmax = fmaxf(tmax, __shfl_xor_sync(0xffffffffu, tmax, 2));
            tmax = fmaxf(tmax, __shfl_xor_sync(0xffffffffu, tmax, 4));
            tmax = fmaxf(tmax, __shfl_xor_sync(0xffffffffu, tmax, 8));
            float mnew = fmaxf(mrow[i], tmax);
            float corr = __expf(mrow[i] - mnew);
            float psum = 0.f;
#pragma unroll
            for (int j = 0; j < 8; j++) {
                s[i][j] = __expf(s[i][j] - mnew);
                psum += s[i][j];
            }
            psum += __shfl_xor_sync(0xffffffffu, psum, 1);
            psum += __shfl_xor_sync(0xffffffffu, psum, 2);
            psum += __shfl_xor_sync(0xffffffffu, psum, 4);
            psum += __shfl_xor_sync(0xffffffffu, psum, 8);
            lrow[i] = lrow[i] * corr + psum;
            mrow[i] = mnew;
            ull cd = dup2(corr);
            mul2ip(oacc[i][0], cd);
            mul2ip(oacc[i][1], cd);
        }

        // ---- store P transposed: psT[c][r] ----
#pragma unroll
        for (int j = 0; j < 8; j++) {
            int c = tx + 16 * j;
            *(float4*)&psT[c * PS_LD + r0] =
                make_float4(s[0][j], s[1][j], s[2][j], s[3][j]);
            *(float4*)&psT[c * PS_LD + r0 + 4] =
                make_float4(s[4][j], s[5][j], s[6][j], s[7][j]);
        }
        __syncthreads();

        // ---- PV: oacc[8 rows][4 d] += P^T rows * V ----
#pragma unroll 4
        for (int c = 0; c < 128; c++) {
            float4 pa = *(float4*)&psT[c * PS_LD + r0];
            float4 pb = *(float4*)&psT[c * PS_LD + r0 + 4];
            ulonglong2 v2 = *(ulonglong2*)&vs[c * KS_LD + d0];
            float p[8] = {pa.x, pa.y, pa.z, pa.w, pb.x, pb.y, pb.z, pb.w};
#pragma unroll
            for (int i = 0; i < 8; i++) {
                ull pd = dup2(p[i]);
                fma2(oacc[i][0], pd, v2.x);
                fma2(oacc[i][1], pd, v2.y);
            }
        }
    }

    // epilogue: scale by 1/l, write O
#pragma unroll
    for (int i = 0; i < 8; i++) {
        ull inv = dup2(1.f / lrow[i]);
        mul2ip(oacc[i][0], inv);
        mul2ip(oacc[i][1], inv);
        *(ulonglong2*)&g_O[base + (size_t)(q0 + r0 + i) * DK_ + d0] =
            make_ulonglong2(oacc[i][0], oacc[i][1]);
    }
}

// ---------------------------------------------------------------------------
// Kernel 3: output projection (FFMA2 microkernel).
// ---------------------------------------------------------------------------
__global__ __launch_bounds__(256) void out_kernel(
    const float* __restrict__ WO, float* __restrict__ Out)
{
    __shared__ __align__(16) float As[BK][BM + 4];
    __shared__ __align__(16) float Bs[BK][BN];

    const int tid = threadIdx.x;
    const int m0 = blockIdx.y * BM;
    const int n0 = blockIdx.x * BN;
    const int tm = (tid >> 4) << 3;
    const int tn = (tid & 15) << 3;

    ull acc2[8][4];
#pragma unroll
    for (int i = 0; i < 8; i++)
#pragma unroll
        for (int j = 0; j < 4; j++) acc2[i][j] = 0ull;

    const int arow = tid >> 2, ac4 = tid & 3;
    const int brow = tid >> 5, bc4 = tid & 31;

    for (int k0 = 0; k0 < D_; k0 += BK) {
#pragma unroll
        for (int p = 0; p < 2; p++) {
            int rr = arow + p * 64;
            int m = m0 + rr;
            int b = m >> 11;
            int s = m & (S_ - 1);
            int k = k0 + ac4 * 4;
            float4 v = *(const float4*)
                &g_O[(((size_t)b * H_ + (k >> 6)) * S_ + s) * DK_ + (k & 63)];
            As[ac4 * 4 + 0][rr] = v.x;
            As[ac4 * 4 + 1][rr] = v.y;
            As[ac4 * 4 + 2][rr] = v.z;
            As[ac4 * 4 + 3][rr] = v.w;
        }
#pragma unroll
        for (int p = 0; p < 2; p++) {
            int kk = brow + p * 8;
            *(float4*)&Bs[kk][bc4 * 4] =
                *(const float4*)&WO[(size_t)(k0 + kk) * D_ + n0 + bc4 * 4];
        }
        __syncthreads();

#pragma unroll
        for (int kk = 0; kk < BK; kk++) {
            float a[8];
            *(float4*)&a[0] = *(float4*)&As[kk][tm];
            *(float4*)&a[4] = *(float4*)&As[kk][tm + 4];
            ulonglong2 b0 = *(ulonglong2*)&Bs[kk][tn];
            ulonglong2 b1 = *(ulonglong2*)&Bs[kk][tn + 4];
            ull bp[4] = {b0.x, b0.y, b1.x, b1.y};
#pragma unroll
            for (int i = 0; i < 8; i++) {
                ull ad = dup2(a[i]);
#pragma unroll
                for (int j = 0; j < 4; j++) fma2(acc2[i][j], ad, bp[j]);
            }
        }
        __syncthreads();
    }

#pragma unroll
    for (int i = 0; i < 8; i++) {
        int m = m0 + tm + i;
        *(ulonglong2*)&Out[(size_t)m * D_ + n0 + tn] =
            make_ulonglong2(acc2[i][0], acc2[i][1]);
        *(ulonglong2*)&Out[(size_t)m * D_ + n0 + tn + 4] =
            make_ulonglong2(acc2[i][2], acc2[i][3]);
    }
}

// ---------------------------------------------------------------------------
extern "C" void kernel_launch(void* const* d_in, const int* in_sizes, int n_in,
                              void* d_out, int out_size)
{
    const float* x  = (const float*)d_in[0];
    const float* WQ = (const float*)d_in[1];
    const float* WK = (const float*)d_in[2];
    const float* WV = (const float*)d_in[3];
    const float* WO = (const float*)d_in[4];
    float* out = (float*)d_out;

    (void)in_sizes; (void)n_in; (void)out_size;

    qkv_kernel<<<dim3(D_ / BN, M_ / BM, 3), 256>>>(x, WQ, WK, WV);

    cudaFuncSetAttribute(attn_kernel,
                         cudaFuncAttributeMaxDynamicSharedMemorySize, ATTN_SMEM);
    attn_kernel<<<dim3(S_ / 128, B_ * H_), 256, ATTN_SMEM>>>();

    out_kernel<<<dim3(D_ / BN, M_ / BM), 256>>>(WO, out);
}

// round 3
// speedup vs baseline: 4.2323x; 2.3425x over previous
#include <cuda_runtime.h>
#include <cuda_bf16.h>

#define B_  4
#define S_  2048
#define D_  1024
#define H_  16
#define DK_ 64
#define M_  (B_*S_)     // 8192
#define BH_ (B_*H_)     // 64

// Scratch: Q/K/V/O stored as bf16 hi/lo pairs (error-compensated split)
__device__ __nv_bfloat16 g_Qh[BH_*S_*DK_], g_Ql[BH_*S_*DK_];
__device__ __nv_bfloat16 g_Kh[BH_*S_*DK_], g_Kl[BH_*S_*DK_];
__device__ __nv_bfloat16 g_Vh[BH_*S_*DK_], g_Vl[BH_*S_*DK_];
__device__ __nv_bfloat16 g_Oh[BH_*S_*DK_], g_Ol[BH_*S_*DK_];

// ---------------------------------------------------------------------------
// helpers
// ---------------------------------------------------------------------------
__device__ __forceinline__ unsigned pk_bf16x2(float lo, float hi) {
    unsigned r;
    asm("cvt.rn.bf16x2.f32 %0, %1, %2;" : "=r"(r) : "f"(hi), "f"(lo));
    return r;
}
// split (x,y) into packed hi bf16x2 and packed residual bf16x2 (lo halves = x)
__device__ __forceinline__ void split_pair(float x, float y, unsigned& h, unsigned& l) {
    h = pk_bf16x2(x, y);
    float hx = __uint_as_float(h << 16);
    float hy = __uint_as_float(h & 0xffff0000u);
    l = pk_bf16x2(x - hx, y - hy);
}
__device__ __forceinline__ unsigned sma(const void* p) {
    return (unsigned)__cvta_generic_to_shared(p);
}
__device__ __forceinline__ void mma_bf16(float* c, const unsigned* a, unsigned b0, unsigned b1) {
    asm("mma.sync.aligned.m16n8k16.row.col.f32.bf16.bf16.f32 "
        "{%0,%1,%2,%3}, {%4,%5,%6,%7}, {%8,%9}, {%0,%1,%2,%3};"
        : "+f"(c[0]), "+f"(c[1]), "+f"(c[2]), "+f"(c[3])
        : "r"(a[0]), "r"(a[1]), "r"(a[2]), "r"(a[3]), "r"(b0), "r"(b1));
}
__device__ __forceinline__ void ldsm_x4(unsigned* r, unsigned a) {
    asm volatile("ldmatrix.sync.aligned.m8n8.x4.shared.b16 {%0,%1,%2,%3}, [%4];"
                 : "=r"(r[0]), "=r"(r[1]), "=r"(r[2]), "=r"(r[3]) : "r"(a));
}
__device__ __forceinline__ void ldsm_x2(unsigned& r0, unsigned& r1, unsigned a) {
    asm volatile("ldmatrix.sync.aligned.m8n8.x2.shared.b16 {%0,%1}, [%2];"
                 : "=r"(r0), "=r"(r1) : "r"(a));
}
__device__ __forceinline__ void ldsm_x2t(unsigned& r0, unsigned& r1, unsigned a) {
    asm volatile("ldmatrix.sync.aligned.m8n8.x2.trans.shared.b16 {%0,%1}, [%2];"
                 : "=r"(r0), "=r"(r1) : "r"(a));
}

#define AS_LD 24    // bf16 units per row (48B): conflict-free LDSM rows
#define BS_LD 136   // 272B rows

// ---------------------------------------------------------------------------
// Kernel 1: QKV projection with bf16-split mma. C = X @ Wcat.
// Block 128m x 128n, 8 warps (each m16 x n128). Epilogue: split-store hi/lo
// bf16 Q/K/V in [BH][S][Dk] layout (softmax scale folded into Q).
// ---------------------------------------------------------------------------
__global__ __launch_bounds__(256) void qkv_kernel(
    const float* __restrict__ X,
    const float* __restrict__ WQ,
    const float* __restrict__ WK,
    const float* __restrict__ WV)
{
    __shared__ __align__(16) __nv_bfloat16 Ash[128 * AS_LD], Asl[128 * AS_LD];
    __shared__ __align__(16) __nv_bfloat16 Bsh[16 * BS_LD],  Bsl[16 * BS_LD];

    const int z = blockIdx.z;
    const float* W = (z == 0) ? WQ : (z == 1) ? WK : WV;
    __nv_bfloat16* Oh = (z == 0) ? g_Qh : (z == 1) ? g_Kh : g_Vh;
    __nv_bfloat16* Ol = (z == 0) ? g_Ql : (z == 1) ? g_Kl : g_Vl;

    const int tid = threadIdx.x, wid = tid >> 5, lane = tid & 31;
    const int m0 = blockIdx.y * 128, n0 = blockIdx.x * 128;

    float oc[16][4];
#pragma unroll
    for (int i = 0; i < 16; i++)
#pragma unroll
        for (int j = 0; j < 4; j++) oc[i][j] = 0.f;

    const unsigned aoff = (unsigned)((wid * 16 + (lane & 15)) * AS_LD + (lane >> 4) * 8);
    const unsigned a_ah = sma(&Ash[aoff]), a_al = sma(&Asl[aoff]);
    const unsigned boff = (unsigned)((lane & 15) * BS_LD);
    const unsigned b_bh = sma(&Bsh[boff]), b_bl = sma(&Bsl[boff]);

    for (int k0 = 0; k0 < D_; k0 += 16) {
        // stage A (X tile 128x16, fp32 -> split bf16)
#pragma unroll
        for (int p = 0; p < 2; p++) {
            int idx = tid + p * 256;
            int row = idx >> 2, c4 = (idx & 3) * 4;
            float4 v = *(const float4*)&X[(size_t)(m0 + row) * D_ + k0 + c4];
            unsigned h0, l0, h1, l1;
            split_pair(v.x, v.y, h0, l0);
            split_pair(v.z, v.w, h1, l1);
            *(unsigned*)&Ash[row * AS_LD + c4]     = h0;
            *(unsigned*)&Ash[row * AS_LD + c4 + 2] = h1;
            *(unsigned*)&Asl[row * AS_LD + c4]     = l0;
            *(unsigned*)&Asl[row * AS_LD + c4 + 2] = l1;
        }
        // stage B (W tile 16x128: [k][n] layout)
#pragma unroll
        for (int p = 0; p < 2; p++) {
            int idx = tid + p * 256;
            int kk = idx >> 5, n = (idx & 31) * 4;
            float4 v = *(const float4*)
                &W[((size_t)((n0 + n) >> 6) * D_ + k0 + kk) * DK_ + ((n0 + n) & 63)];
            unsigned h0, l0, h1, l1;
            split_pair(v.x, v.y, h0, l0);
            split_pair(v.z, v.w, h1, l1);
            *(unsigned*)&Bsh[kk * BS_LD + n]     = h0;
            *(unsigned*)&Bsh[kk * BS_LD + n + 2] = h1;
            *(unsigned*)&Bsl[kk * BS_LD + n]     = l0;
            *(unsigned*)&Bsl[kk * BS_LD + n + 2] = l1;
        }
        __syncthreads();

        unsigned ah[4], al[4];
        ldsm_x4(ah, a_ah);
        ldsm_x4(al, a_al);
#pragma unroll
        for (int nt = 0; nt < 16; nt++) {
            unsigned bh0, bh1, bl0, bl1;
            ldsm_x2t(bh0, bh1, b_bh + nt * 16);
            ldsm_x2t(bl0, bl1, b_bl + nt * 16);
            mma_bf16(oc[nt], ah, bh0, bh1);
            mma_bf16(oc[nt], ah, bl0, bl1);
            mma_bf16(oc[nt], al, bh0, bh1);
        }
        __syncthreads();
    }

    // epilogue: split-store
    const int g = lane >> 2, t = lane & 3;
    const float scale = (z == 0) ? 0.125f : 1.0f;
#pragma unroll
    for (int nt = 0; nt < 16; nt++) {
        int n = n0 + nt * 8 + 2 * t;
        int h = n >> 6, d = n & 63;
        int m = m0 + wid * 16 + g;
        int b = m >> 11, s = m & (S_ - 1);
        size_t idx = ((size_t)(b * H_ + h) * S_ + s) * DK_ + d;
        unsigned ph, pl;
        split_pair(oc[nt][0] * scale, oc[nt][1] * scale, ph, pl);
        *(unsigned*)&Oh[idx] = ph;
        *(unsigned*)&Ol[idx] = pl;
        int m2 = m + 8;
        size_t idx2 = ((size_t)(b * H_ + h) * S_ + (m2 & (S_ - 1))) * DK_ + d;
        split_pair(oc[nt][2] * scale, oc[nt][3] * scale, ph, pl);
        *(unsigned*)&Oh[idx2] = ph;
        *(unsigned*)&Ol[idx2] = pl;
    }
}

// ---------------------------------------------------------------------------
// Kernel 2: FA2-style flash attention, bf16-split mma.
// Block: 128 q-rows x one (b,h); 8 warps, each 16 q-rows. KV tiles of 64.
// Scores and P live in registers; D-frag of QK^T repacks into A-frag of PV.
// ---------------------------------------------------------------------------
#define KV_LD 72

__global__ __launch_bounds__(256) void attn_kernel() {
    __shared__ __align__(16) __nv_bfloat16 kvs[4 * 64 * KV_LD];  // 36,864 B
    __nv_bfloat16* Ksh = kvs;
    __nv_bfloat16* Ksl = kvs + 64 * KV_LD;
    __nv_bfloat16* Vsh = kvs + 2 * 64 * KV_LD;
    __nv_bfloat16* Vsl = kvs + 3 * 64 * KV_LD;

    const int tid = threadIdx.x, wid = tid >> 5, lane = tid & 31;
    const int g = lane >> 2, t = lane & 3;
    const int bh = blockIdx.y;
    const int q0 = blockIdx.x * 128;
    const size_t base = (size_t)bh * S_ * DK_;

    // ---- stage Q (hi then lo) through smem, hoist fragments ----
    unsigned qh[4][4], ql[4][4];
#pragma unroll
    for (int pass = 0; pass < 2; pass++) {
        const __nv_bfloat16* src = pass ? g_Ql : g_Qh;
        for (int i = tid; i < 1024; i += 256) {
            int row = i >> 3, c8 = (i & 7) * 8;
            *(uint4*)&kvs[row * KV_LD + c8] =
                *(const uint4*)&src[base + (size_t)(q0 + row) * DK_ + c8];
        }
        __syncthreads();
        unsigned ad = sma(&kvs[(wid * 16 + (lane & 15)) * KV_LD + (lane >> 4) * 8]);
#pragma unroll
        for (int kt = 0; kt < 4; kt++)
            ldsm_x4(pass ? ql[kt] : qh[kt], ad + kt * 32);
        __syncthreads();
    }

    float oc[8][4];
#pragma unroll
    for (int i = 0; i < 8; i++)
#pragma unroll
        for (int j = 0; j < 4; j++) oc[i][j] = 0.f;
    float m0r = -1e30f, m1r = -1e30f, l0r = 0.f, l1r = 0.f;

    // smem byte offsets for LDSM (per lane)
    const unsigned k_row = (unsigned)((lane & 7) * KV_LD + (lane & 8));      // +nt*8 rows, +kt*16 cols
    const unsigned v_row = (unsigned)((lane & 15) * KV_LD);                  // +kt*16 rows, +nt*8 cols
    const unsigned kh_b = sma(Ksh), kl_b = sma(Ksl);
    const unsigned vh_b = sma(Vsh), vl_b = sma(Vsl);

    const int arr = tid >> 6, tt = tid & 63;
    const __nv_bfloat16* gsrc = (arr == 0) ? g_Kh : (arr == 1) ? g_Kl
                              : (arr == 2) ? g_Vh : g_Vl;
    __nv_bfloat16* dst = kvs + arr * 64 * KV_LD;

    for (int kv0 = 0; kv0 < S_; kv0 += 64) {
        __syncthreads();
        // load K/V hi/lo tiles (each 64-thread group owns one array)
#pragma unroll
        for (int u = 0; u < 8; u++) {
            int idx = tt + 64 * u;
            int row = idx >> 3, c8 = (idx & 7) * 8;
            *(uint4*)&dst[row * KV_LD + c8] =
                *(const uint4*)&gsrc[base + (size_t)(kv0 + row) * DK_ + c8];
        }
        __syncthreads();

        // ---- scores S = Q K^T (3-term split) ----
        float sc[8][4];
#pragma unroll
        for (int i = 0; i < 8; i++)
#pragma unroll
            for (int j = 0; j < 4; j++) sc[i][j] = 0.f;
#pragma unroll
        for (int nt = 0; nt < 8; nt++) {
#pragma unroll
            for (int kt = 0; kt < 4; kt++) {
                unsigned off = (k_row + (unsigned)(nt * 8 * KV_LD + kt * 16)) * 2;
                unsigned h0, h1, l0, l1;
                ldsm_x2(h0, h1, kh_b + off);
                ldsm_x2(l0, l1, kl_b + off);
                mma_bf16(sc[nt], qh[kt], h0, h1);
                mma_bf16(sc[nt], qh[kt], l0, l1);
                mma_bf16(sc[nt], ql[kt], h0, h1);
            }
        }

        // ---- online softmax (rows g and g+8 per lane) ----
        float mx0 = sc[0][0], mx1 = sc[0][2];
#pragma unroll
        for (int nt = 0; nt < 8; nt++) {
            mx0 = fmaxf(mx0, fmaxf(sc[nt][0], sc[nt][1]));
            mx1 = fmaxf(mx1, fmaxf(sc[nt][2], sc[nt][3]));
        }
        mx0 = fmaxf(mx0, __shfl_xor_sync(0xffffffffu, mx0, 1));
        mx0 = fmaxf(mx0, __shfl_xor_sync(0xffffffffu, mx0, 2));
        mx1 = fmaxf(mx1, __shfl_xor_sync(0xffffffffu, mx1, 1));
        mx1 = fmaxf(mx1, __shfl_xor_sync(0xffffffffu, mx1, 2));
        float mn0 = fmaxf(m0r, mx0), mn1 = fmaxf(m1r, mx1);
        float cr0 = __expf(m0r - mn0), cr1 = __expf(m1r - mn1);
        m0r = mn0; m1r = mn1;
        float s0 = 0.f, s1 = 0.f;
#pragma unroll
        for (int nt = 0; nt < 8; nt++) {
            sc[nt][0] = __expf(sc[nt][0] - mn0);
            sc[nt][1] = __expf(sc[nt][1] - mn0);
            sc[nt][2] = __expf(sc[nt][2] - mn1);
            sc[nt][3] = __expf(sc[nt][3] - mn1);
            s0 += sc[nt][0] + sc[nt][1];
            s1 += sc[nt][2] + sc[nt][3];
        }
        s0 += __shfl_xor_sync(0xffffffffu, s0, 1);
        s0 += __shfl_xor_sync(0xffffffffu, s0, 2);
        s1 += __shfl_xor_sync(0xffffffffu, s1, 1);
        s1 += __shfl_xor_sync(0xffffffffu, s1, 2);
        l0r = l0r * cr0 + s0;
        l1r = l1r * cr1 + s1;
#pragma unroll
        for (int nt = 0; nt < 8; nt++) {
            oc[nt][0] *= cr0; oc[nt][1] *= cr0;
            oc[nt][2] *= cr1; oc[nt][3] *= cr1;
        }

        // ---- pack P into PV A-fragments (hi/lo) ----
        unsigned pah[4][4], pal[4][4];
#pragma unroll
        for (int kt = 0; kt < 4; kt++) {
            int j0 = 2 * kt, j1 = 2 * kt + 1;
            split_pair(sc[j0][0], sc[j0][1], pah[kt][0], pal[kt][0]);
            split_pair(sc[j0][2], sc[j0][3], pah[kt][1], pal[kt][1]);
            split_pair(sc[j1][0], sc[j1][1], pah[kt][2], pal[kt][2]);
            split_pair(sc[j1][2], sc[j1][3], pah[kt][3], pal[kt][3]);
        }

        // ---- PV: O += P V (3-term split) ----
#pragma unroll
        for (int nt = 0; nt < 8; nt++) {
#pragma unroll
            for (int kt = 0; kt < 4; kt++) {
                unsigned off = (v_row + (unsigned)(kt * 16 * KV_LD + nt * 8)) * 2;
                unsigned h0, h1, l0, l1;
                ldsm_x2t(h0, h1, vh_b + off);
                ldsm_x2t(l0, l1, vl_b + off);
                mma_bf16(oc[nt], pah[kt], h0, h1);
                mma_bf16(oc[nt], pah[kt], l0, l1);
                mma_bf16(oc[nt], pal[kt], h0, h1);
            }
        }
    }

    // ---- epilogue: normalize, split-store O ----
    const float i0 = 1.f / l0r, i1 = 1.f / l1r;
    const int r = q0 + wid * 16 + g;
#pragma unroll
    for (int nt = 0; nt < 8; nt++) {
        int d = nt * 8 + 2 * t;
        unsigned ph, pl;
        split_pair(oc[nt][0] * i0, oc[nt][1] * i0, ph, pl);
        *(unsigned*)&g_Oh[base + (size_t)r * DK_ + d] = ph;
        *(unsigned*)&g_Ol[base + (size_t)r * DK_ + d] = pl;
        split_pair(oc[nt][2] * i1, oc[nt][3] * i1, ph, pl);
        *(unsigned*)&g_Oh[base + (size_t)(r + 8) * DK_ + d] = ph;
        *(unsigned*)&g_Ol[base + (size_t)(r + 8) * DK_ + d] = pl;
    }
}

// ---------------------------------------------------------------------------
// Kernel 3: output projection, bf16-split mma. out = Ocat @ WO (fp32 out).
// A comes pre-split from attention (g_Oh/g_Ol).
// ---------------------------------------------------------------------------
__global__ __launch_bounds__(256) void out_kernel(
    const float* __restrict__ WO, float* __restrict__ Out)
{
    __shared__ __align__(16) __nv_bfloat16 Ash[128 * AS_LD], Asl[128 * AS_LD];
    __shared__ __align__(16) __nv_bfloat16 Bsh[16 * BS_LD],  Bsl[16 * BS_LD];

    const int tid = threadIdx.x, wid = tid >> 5, lane = tid & 31;
    const int m0 = blockIdx.y * 128, n0 = blockIdx.x * 128;

    float oc[16][4];
#pragma unroll
    for (int i = 0; i < 16; i++)
#pragma unroll
        for (int j = 0; j < 4; j++) oc[i][j] = 0.f;

    const unsigned aoff = (unsigned)((wid * 16 + (lane & 15)) * AS_LD + (lane >> 4) * 8);
    const unsigned a_ah = sma(&Ash[aoff]), a_al = sma(&Asl[aoff]);
    const unsigned boff = (unsigned)((lane & 15) * BS_LD);
    const unsigned b_bh = sma(&Bsh[boff]), b_bl = sma(&Bsl[boff]);

    for (int k0 = 0; k0 < D_; k0 += 16) {
        // stage A from pre-split g_Oh/g_Ol (no conversion)
#pragma unroll
        for (int p = 0; p < 2; p++) {
            int idx = tid + p * 256;
            int isLo = idx >> 8, rem = idx & 255;
            int row = rem >> 1, half = rem & 1;
            int m = m0 + row;
            int b = m >> 11, s = m & (S_ - 1);
            size_t src = ((size_t)(b * H_ + (k0 >> 6)) * S_ + s) * DK_ + (k0 & 63) + half * 8;
            __nv_bfloat16* dstp = isLo ? Asl : Ash;
            const __nv_bfloat16* srcp = isLo ? g_Ol : g_Oh;
            *(uint4*)&dstp[row * AS_LD + half * 8] = *(const uint4*)&srcp[src];
        }
        // stage B (WO tile 16x128, fp32 -> split)
#pragma unroll
        for (int p = 0; p < 2; p++) {
            int idx = tid + p * 256;
            int kk = idx >> 5, n = (idx & 31) * 4;
            float4 v = *(const float4*)&WO[(size_t)(k0 + kk) * D_ + n0 + n];
            unsigned h0, l0, h1, l1;
            split_pair(v.x, v.y, h0, l0);
            split_pair(v.z, v.w, h1, l1);
            *(unsigned*)&Bsh[kk * BS_LD + n]     = h0;
            *(unsigned*)&Bsh[kk * BS_LD + n + 2] = h1;
            *(unsigned*)&Bsl[kk * BS_LD + n]     = l0;
            *(unsigned*)&Bsl[kk * BS_LD + n + 2] = l1;
        }
        __syncthreads();

        unsigned ah[4], al[4];
        ldsm_x4(ah, a_ah);
        ldsm_x4(al, a_al);
#pragma unroll
        for (int nt = 0; nt < 16; nt++) {
            unsigned bh0, bh1, bl0, bl1;
            ldsm_x2t(bh0, bh1, b_bh + nt * 16);
            ldsm_x2t(bl0, bl1, b_bl + nt * 16);
            mma_bf16(oc[nt], ah, bh0, bh1);
            mma_bf16(oc[nt], ah, bl0, bl1);
            mma_bf16(oc[nt], al, bh0, bh1);
        }
        __syncthreads();
    }

    const int g = lane >> 2, t = lane & 3;
#pragma unroll
    for (int nt = 0; nt < 16; nt++) {
        int n = n0 + nt * 8 + 2 * t;
        int m = m0 + wid * 16 + g;
        *(float2*)&Out[(size_t)m * D_ + n]       = make_float2(oc[nt][0], oc[nt][1]);
        *(float2*)&Out[(size_t)(m + 8) * D_ + n] = make_float2(oc[nt][2], oc[nt][3]);
    }
}

// ---------------------------------------------------------------------------
extern "C" void kernel_launch(void* const* d_in, const int* in_sizes, int n_in,
                              void* d_out, int out_size)
{
    const float* x  = (const float*)d_in[0];
    const float* WQ = (const float*)d_in[1];
    const float* WK = (const float*)d_in[2];
    const float* WV = (const float*)d_in[3];
    const float* WO = (const float*)d_in[4];
    float* out = (float*)d_out;

    (void)in_sizes; (void)n_in; (void)out_size;

    qkv_kernel<<<dim3(D_ / 128, M_ / 128, 3), 256>>>(x, WQ, WK, WV);
    attn_kernel<<<dim3(S_ / 128, BH_), 256>>>();
    out_kernel<<<dim3(D_ / 128, M_ / 128), 256>>>(WO, out);
}

// round 6
// speedup vs baseline: 4.5064x; 1.0648x over previous
#include <cuda_runtime.h>
#include <cuda_bf16.h>

#define B_  4
#define S_  2048
#define D_  1024
#define H_  16
#define DK_ 64
#define M_  (B_*S_)     // 8192
#define BH_ (B_*H_)     // 64

// Pre-split bf16 hi/lo operands (written once per launch by split kernels)
__device__ __nv_bfloat16 g_Xh[M_*D_],    g_Xl[M_*D_];
__device__ __nv_bfloat16 g_Wh[3*D_*D_],  g_Wl[3*D_*D_];
__device__ __nv_bfloat16 g_WOh[D_*D_],   g_WOl[D_*D_];
__device__ __nv_bfloat16 g_Qh[BH_*S_*DK_], g_Ql[BH_*S_*DK_];
__device__ __nv_bfloat16 g_Kh[BH_*S_*DK_], g_Kl[BH_*S_*DK_];
__device__ __nv_bfloat16 g_Vh[BH_*S_*DK_], g_Vl[BH_*S_*DK_];
__device__ __nv_bfloat16 g_Oh[BH_*S_*DK_], g_Ol[BH_*S_*DK_];

// ---------------------------------------------------------------------------
// helpers
// ---------------------------------------------------------------------------
__device__ __forceinline__ unsigned pk_bf16x2(float lo, float hi) {
    unsigned r;
    asm("cvt.rn.bf16x2.f32 %0, %1, %2;" : "=r"(r) : "f"(hi), "f"(lo));
    return r;
}
__device__ __forceinline__ void split_pair(float x, float y, unsigned& h, unsigned& l) {
    h = pk_bf16x2(x, y);
    float hx = __uint_as_float(h << 16);
    float hy = __uint_as_float(h & 0xffff0000u);
    l = pk_bf16x2(x - hx, y - hy);
}
__device__ __forceinline__ unsigned sma(const void* p) {
    return (unsigned)__cvta_generic_to_shared(p);
}
__device__ __forceinline__ void mma_bf16(float* c, const unsigned* a, unsigned b0, unsigned b1) {
    asm("mma.sync.aligned.m16n8k16.row.col.f32.bf16.bf16.f32 "
        "{%0,%1,%2,%3}, {%4,%5,%6,%7}, {%8,%9}, {%0,%1,%2,%3};"
        : "+f"(c[0]), "+f"(c[1]), "+f"(c[2]), "+f"(c[3])
        : "r"(a[0]), "r"(a[1]), "r"(a[2]), "r"(a[3]), "r"(b0), "r"(b1));
}
__device__ __forceinline__ void ldsm_x4(unsigned* r, unsigned a) {
    asm volatile("ldmatrix.sync.aligned.m8n8.x4.shared.b16 {%0,%1,%2,%3}, [%4];"
                 : "=r"(r[0]), "=r"(r[1]), "=r"(r[2]), "=r"(r[3]) : "r"(a));
}
__device__ __forceinline__ void ldsm_x4t(unsigned* r, unsigned a) {
    asm volatile("ldmatrix.sync.aligned.m8n8.x4.trans.shared.b16 {%0,%1,%2,%3}, [%4];"
                 : "=r"(r[0]), "=r"(r[1]), "=r"(r[2]), "=r"(r[3]) : "r"(a));
}
#define CP16(dst, src) \
    asm volatile("cp.async.cg.shared.global [%0], [%1], 16;" :: "r"(dst), "l"(src) : "memory")
#define CPCOMMIT() asm volatile("cp.async.commit_group;" ::: "memory")
#define CPWAIT1()  asm volatile("cp.async.wait_group 1;" ::: "memory")
#define CPWAIT0()  asm volatile("cp.async.wait_group 0;" ::: "memory")

// ---------------------------------------------------------------------------
// Split kernels: fp32 -> (hi, lo) bf16 pairs.
// ---------------------------------------------------------------------------
__global__ __launch_bounds__(256) void split_x_kernel(const float* __restrict__ src) {
    size_t i = (size_t)blockIdx.x * 256 + threadIdx.x;      // 8-elem groups
    float4 v0 = *(const float4*)(src + i * 8);
    float4 v1 = *(const float4*)(src + i * 8 + 4);
    unsigned h0,l0,h1,l1,h2,l2,h3,l3;
    split_pair(v0.x, v0.y, h0, l0); split_pair(v0.z, v0.w, h1, l1);
    split_pair(v1.x, v1.y, h2, l2); split_pair(v1.z, v1.w, h3, l3);
    *(uint4*)(g_Xh + i * 8) = make_uint4(h0, h1, h2, h3);
    *(uint4*)(g_Xl + i * 8) = make_uint4(l0, l1, l2, l3);
}
__global__ __launch_bounds__(256) void split_wo_kernel(const float* __restrict__ src) {
    size_t i = (size_t)blockIdx.x * 256 + threadIdx.x;
    float4 v0 = *(const float4*)(src + i * 8);
    float4 v1 = *(const float4*)(src + i * 8 + 4);
    unsigned h0,l0,h1,l1,h2,l2,h3,l3;
    split_pair(v0.x, v0.y, h0, l0); split_pair(v0.z, v0.w, h1, l1);
    split_pair(v1.x, v1.y, h2, l2); split_pair(v1.z, v1.w, h3, l3);
    *(uint4*)(g_WOh + i * 8) = make_uint4(h0, h1, h2, h3);
    *(uint4*)(g_WOl + i * 8) = make_uint4(l0, l1, l2, l3);
}
// W[h][d][dk] (x3) -> [z][d][h*64+dk]
__global__ __launch_bounds__(256) void split_wqkv_kernel(
    const float* __restrict__ WQ, const float* __restrict__ WK, const float* __restrict__ WV)
{
    unsigned i = blockIdx.x * 256 + threadIdx.x;            // 393216 groups of 8
    int o8 = (i & 7) * 8;
    int d  = (i >> 3) & 1023;
    int h  = (i >> 13) & 15;
    int z  = i >> 17;
    const float* src = ((z == 0) ? WQ : (z == 1) ? WK : WV) + ((size_t)h * D_ + d) * DK_ + o8;
    float4 v0 = *(const float4*)(src);
    float4 v1 = *(const float4*)(src + 4);
    unsigned h0,l0,h1,l1,h2,l2,h3,l3;
    split_pair(v0.x, v0.y, h0, l0); split_pair(v0.z, v0.w, h1, l1);
    split_pair(v1.x, v1.y, h2, l2); split_pair(v1.z, v1.w, h3, l3);
    size_t dst = (size_t)z * D_ * D_ + (size_t)d * D_ + h * 64 + o8;
    *(uint4*)(g_Wh + dst) = make_uint4(h0, h1, h2, h3);
    *(uint4*)(g_Wl + dst) = make_uint4(l0, l1, l2, l3);
}

// ---------------------------------------------------------------------------
// GEMM tiling constants (shared by qkv / out kernels)
// ---------------------------------------------------------------------------
#define AS_LD 40        // A row stride (bf16): 80B, LDSM conflict-free
#define BS_LD 136       // B row stride: 272B
#define A_SPLIT 5120    // 128*40
#define A_STAGE 10240
#define B_OFF   20480
#define B_SPLIT 4352    // 32*136
#define B_STAGE 8704
#define GEMM_SMEM_BYTES ((A_STAGE*2 + B_STAGE*2) * 2)   // 75776

// ---------------------------------------------------------------------------
// Kernel: QKV projection. Pure bf16 split-GEMM, cp.async double-buffered.
// Block 128m x 128n; 8 warps as 4m x 2n (warp tile m32 x n64).
// ---------------------------------------------------------------------------
__global__ __launch_bounds__(256, 2) void qkv_kernel() {
    extern __shared__ __align__(16) __nv_bfloat16 smg[];
    const unsigned sb = sma(smg);
    const int z = blockIdx.z;
    const __nv_bfloat16* Bh = g_Wh + (size_t)z * D_ * D_;
    const __nv_bfloat16* Bl = g_Wl + (size_t)z * D_ * D_;
    __nv_bfloat16* Oh = (z == 0) ? g_Qh : (z == 1) ? g_Kh : g_Vh;
    __nv_bfloat16* Ol = (z == 0) ? g_Ql : (z == 1) ? g_Kl : g_Vl;

    const int tid = threadIdx.x, wid = tid >> 5, lane = tid & 31;
    const int wm = wid & 3, wn = wid >> 2;
    const int m0 = blockIdx.y * 128, n0 = blockIdx.x * 128;

    float oc[2][8][4];
#pragma unroll
    for (int a = 0; a < 2; a++)
#pragma unroll
        for (int b = 0; b < 8; b++)
#pragma unroll
            for (int c = 0; c < 4; c++) oc[a][b][c] = 0.f;

    auto stage = [&](int k0, int st) {
#pragma unroll
        for (int u = 0; u < 4; u++) {                       // A: 128x32 hi+lo
            int sp = u >> 1, rem = tid + (u & 1) * 256;
            int row = rem >> 2, ch = (rem & 3) * 8;
            const __nv_bfloat16* s = (sp ? g_Xl : g_Xh) + (size_t)(m0 + row) * D_ + k0 + ch;
            CP16(sb + (st * A_STAGE + sp * A_SPLIT + row * AS_LD + ch) * 2, s);
        }
#pragma unroll
        for (int u = 0; u < 4; u++) {                       // B: 32x128 hi+lo
            int sp = u >> 1, rem = tid + (u & 1) * 256;
            int row = rem >> 4, ch = (rem & 15) * 8;
            const __nv_bfloat16* s = (sp ? Bl : Bh) + (size_t)(k0 + row) * D_ + n0 + ch;
            CP16(sb + (B_OFF + st * B_STAGE + sp * B_SPLIT + row * BS_LD + ch) * 2, s);
        }
    };

    stage(0, 0); CPCOMMIT();

    const int arow = lane & 15, acol = (lane >> 4) * 8;
    const int brow = lane & 15, bcol = (lane & 16) >> 1;

    int st = 0;
    for (int k0 = 0; k0 < D_; k0 += 32) {
        if (k0 + 32 < D_) { stage(k0 + 32, st ^ 1); CPCOMMIT(); CPWAIT1(); }
        else CPWAIT0();
        __syncthreads();
#pragma unroll
        for (int h = 0; h < 2; h++) {
            unsigned ah[2][4], al[2][4];
#pragma unroll
            for (int mi = 0; mi < 2; mi++) {
                unsigned ao = sb + (st * A_STAGE + (wm * 32 + mi * 16 + arow) * AS_LD
                                    + acol + h * 16) * 2;
                ldsm_x4(ah[mi], ao);
                ldsm_x4(al[mi], ao + A_SPLIT * 2);
            }
#pragma unroll
            for (int p = 0; p < 4; p++) {
                unsigned bo = sb + (B_OFF + st * B_STAGE + (h * 16 + brow) * BS_LD
                                    + wn * 64 + p * 16 + bcol) * 2;
                unsigned bhf[4], blf[4];
                ldsm_x4t(bhf, bo);
                ldsm_x4t(blf, bo + B_SPLIT * 2);
#pragma unroll
                for (int mi = 0; mi < 2; mi++) {
                    mma_bf16(oc[mi][2*p],   ah[mi], bhf[0], bhf[1]);
                    mma_bf16(oc[mi][2*p],   ah[mi], blf[0], blf[1]);
                    mma_bf16(oc[mi][2*p],   al[mi], bhf[0], bhf[1]);
                    mma_bf16(oc[mi][2*p+1], ah[mi], bhf[2], bhf[3]);
                    mma_bf16(oc[mi][2*p+1], ah[mi], blf[2], blf[3]);
                    mma_bf16(oc[mi][2*p+1], al[mi], bhf[2], bhf[3]);
                }
            }
        }
        __syncthreads();
        st ^= 1;
    }

    // epilogue: split-store into [BH][S][Dk]
    const int g = lane >> 2, t = lane & 3;
    const float scale = (z == 0) ? 0.125f : 1.0f;
#pragma unroll
    for (int mi = 0; mi < 2; mi++)
#pragma unroll
        for (int nt = 0; nt < 8; nt++) {
            int n = n0 + wn * 64 + nt * 8 + 2 * t;
            int hh = n >> 6, d = n & 63;
            int m = m0 + wm * 32 + mi * 16 + g;
            int b = m >> 11, s = m & (S_ - 1);
            size_t idx = ((size_t)(b * H_ + hh) * S_ + s) * DK_ + d;
            unsigned ph, pl;
            split_pair(oc[mi][nt][0] * scale, oc[mi][nt][1] * scale, ph, pl);
            *(unsigned*)&Oh[idx] = ph;  *(unsigned*)&Ol[idx] = pl;
            split_pair(oc[mi][nt][2] * scale, oc[mi][nt][3] * scale, ph, pl);
            *(unsigned*)&Oh[idx + 8 * DK_] = ph;  *(unsigned*)&Ol[idx + 8 * DK_] = pl;
        }
}

// ---------------------------------------------------------------------------
// Kernel: output projection. Same GEMM, A pre-split from attention.
// ---------------------------------------------------------------------------
__global__ __launch_bounds__(256, 2) void out_kernel(float* __restrict__ Out) {
    extern __shared__ __align__(16) __nv_bfloat16 smg[];
    const unsigned sb = sma(smg);
    const int tid = threadIdx.x, wid = tid >> 5, lane = tid & 31;
    const int wm = wid & 3, wn = wid >> 2;
    const int m0 = blockIdx.y * 128, n0 = blockIdx.x * 128;

    float oc[2][8][4];
#pragma unroll
    for (int a = 0; a < 2; a++)
#pragma unroll
        for (int b = 0; b < 8; b++)
#pragma unroll
            for (int c = 0; c < 4; c++) oc[a][b][c] = 0.f;

    auto stage = [&](int k0, int st) {
#pragma unroll
        for (int u = 0; u < 4; u++) {                       // A from g_Oh/g_Ol
            int sp = u >> 1, rem = tid + (u & 1) * 256;
            int row = rem >> 2, ch = (rem & 3) * 8;
            int m = m0 + row, b = m >> 11, s = m & (S_ - 1);
            const __nv_bfloat16* src = (sp ? g_Ol : g_Oh)
                + ((size_t)(b * H_ + (k0 >> 6)) * S_ + s) * DK_ + (k0 & 63) + ch;
            CP16(sb + (st * A_STAGE + sp * A_SPLIT + row * AS_LD + ch) * 2, src);
        }
#pragma unroll
        for (int u = 0; u < 4; u++) {                       // B from g_WOh/g_WOl
            int sp = u >> 1, rem = tid + (u & 1) * 256;
            int row = rem >> 4, ch = (rem & 15) * 8;
            const __nv_bfloat16* src = (sp ? g_WOl : g_WOh)
                + (size_t)(k0 + row) * D_ + n0 + ch;
            CP16(sb + (B_OFF + st * B_STAGE + sp * B_SPLIT + row * BS_LD + ch) * 2, src);
        }
    };

    stage(0, 0); CPCOMMIT();

    const int arow = lane & 15, acol = (lane >> 4) * 8;
    const int brow = lane & 15, bcol = (lane & 16) >> 1;

    int st = 0;
    for (int k0 = 0; k0 < D_; k0 += 32) {
        if (k0 + 32 < D_) { stage(k0 + 32, st ^ 1); CPCOMMIT(); CPWAIT1(); }
        else CPWAIT0();
        __syncthreads();
#pragma unroll
        for (int h = 0; h < 2; h++) {
            unsigned ah[2][4], al[2][4];
#pragma unroll
            for (int mi = 0; mi < 2; mi++) {
                unsigned ao = sb + (st * A_STAGE + (wm * 32 + mi * 16 + arow) * AS_LD
                                    + acol + h * 16) * 2;
                ldsm_x4(ah[mi], ao);
                ldsm_x4(al[mi], ao + A_SPLIT * 2);
            }
#pragma unroll
            for (int p = 0; p < 4; p++) {
                unsigned bo = sb + (B_OFF + st * B_STAGE + (h * 16 + brow) * BS_LD
                                    + wn * 64 + p * 16 + bcol) * 2;
                unsigned bhf[4], blf[4];
                ldsm_x4t(bhf, bo);
                ldsm_x4t(blf, bo + B_SPLIT * 2);
#pragma unroll
                for (int mi = 0; mi < 2; mi++) {
                    mma_bf16(oc[mi][2*p],   ah[mi], bhf[0], bhf[1]);
                    mma_bf16(oc[mi][2*p],   ah[mi], blf[0], blf[1]);
                    mma_bf16(oc[mi][2*p],   al[mi], bhf[0], bhf[1]);
                    mma_bf16(oc[mi][2*p+1], ah[mi], bhf[2], bhf[3]);
                    mma_bf16(oc[mi][2*p+1], ah[mi], blf[2], blf[3]);
                    mma_bf16(oc[mi][2*p+1], al[mi], bhf[2], bhf[3]);
                }
            }
        }
        __syncthreads();
        st ^= 1;
    }

    const int g = lane >> 2, t = lane & 3;
#pragma unroll
    for (int mi = 0; mi < 2; mi++)
#pragma unroll
        for (int nt = 0; nt < 8; nt++) {
            int n = n0 + wn * 64 + nt * 8 + 2 * t;
            int m = m0 + wm * 32 + mi * 16 + g;
            *(float2*)&Out[(size_t)m * D_ + n] = make_float2(oc[mi][nt][0], oc[mi][nt][1]);
            *(float2*)&Out[(size_t)(m + 8) * D_ + n] = make_float2(oc[mi][nt][2], oc[mi][nt][3]);
        }
}

// ---------------------------------------------------------------------------
// Kernel: flash attention. cp.async double-buffered KV, ldsm.x4 everywhere.
// Block: 128 q-rows x one (b,h); 8 warps x 16 q-rows; KV tiles of 64.
// ---------------------------------------------------------------------------
#define KV_LD 72
#define KV_ARR 4608       // 64*72
#define KV_STAGE 18432    // 4 arrays
#define ATTN_SMEM_BYTES (KV_STAGE * 2 * 2)   // 73728

__global__ __launch_bounds__(256) void attn_kernel() {
    extern __shared__ __align__(16) __nv_bfloat16 smg[];
    const unsigned sb = sma(smg);
    const int tid = threadIdx.x, wid = tid >> 5, lane = tid & 31;
    const int g = lane >> 2, t = lane & 3;
    const int bh = blockIdx.y, q0 = blockIdx.x * 128;
    const size_t base = (size_t)bh * S_ * DK_;

    // ---- hoist Q fragments (hi then lo) via smem ----
    unsigned qh[4][4], ql[4][4];
#pragma unroll
    for (int pass = 0; pass < 2; pass++) {
        const __nv_bfloat16* src = pass ? g_Ql : g_Qh;
        for (int i = tid; i < 1024; i += 256) {
            int row = i >> 3, c8 = (i & 7) * 8;
            *(uint4*)&smg[row * KV_LD + c8] =
                *(const uint4*)&src[base + (size_t)(q0 + row) * DK_ + c8];
        }
        __syncthreads();
        unsigned ad = sb + ((wid * 16 + (lane & 15)) * KV_LD + (lane >> 4) * 8) * 2;
#pragma unroll
        for (int kt = 0; kt < 4; kt++)
            ldsm_x4(pass ? ql[kt] : qh[kt], ad + kt * 32);
        __syncthreads();
    }

    float oc[8][4];
#pragma unroll
    for (int i = 0; i < 8; i++)
#pragma unroll
        for (int j = 0; j < 4; j++) oc[i][j] = 0.f;
    float m0r = -1e30f, m1r = -1e30f, l0r = 0.f, l1r = 0.f;

    // lane-group LDSM base offsets (bytes)
    const unsigned kb = (((lane & 7) + ((lane & 16) >> 1)) * KV_LD + (lane & 8)) * 2;
    const unsigned vb = ((lane & 15) * KV_LD + ((lane & 16) >> 1)) * 2;

    auto stage = [&](int kv0, int st) {
#pragma unroll
        for (int u = 0; u < 8; u++) {
            int arr = u >> 1, rem = tid + (u & 1) * 256;
            int row = rem >> 3, ch = (rem & 7) * 8;
            const __nv_bfloat16* s =
                (arr == 0 ? g_Kh : arr == 1 ? g_Kl : arr == 2 ? g_Vh : g_Vl)
                + base + (size_t)(kv0 + row) * DK_ + ch;
            CP16(sb + (st * KV_STAGE + arr * KV_ARR + row * KV_LD + ch) * 2, s);
        }
    };

    stage(0, 0); CPCOMMIT();

    int st = 0;
    for (int kv0 = 0; kv0 < S_; kv0 += 64) {
        if (kv0 + 64 < S_) { stage(kv0 + 64, st ^ 1); CPCOMMIT(); CPWAIT1(); }
        else CPWAIT0();
        __syncthreads();

        const unsigned kH = sb + (st * KV_STAGE) * 2 + kb;
        const unsigned kL = kH + KV_ARR * 2;
        const unsigned vH = sb + (st * KV_STAGE + 2 * KV_ARR) * 2 + vb;
        const unsigned vL = vH + KV_ARR * 2;

        // ---- scores ----
        float sc[8][4];
#pragma unroll
        for (int i = 0; i < 8; i++)
#pragma unroll
            for (int j = 0; j < 4; j++) sc[i][j] = 0.f;
#pragma unroll
        for (int p = 0; p < 4; p++) {
#pragma unroll
            for (int kt = 0; kt < 4; kt++) {
                unsigned off = (unsigned)(p * 16 * KV_LD + kt * 16) * 2;
                unsigned hf[4], lf[4];
                ldsm_x4(hf, kH + off);
                ldsm_x4(lf, kL + off);
                mma_bf16(sc[2*p],   qh[kt], hf[0], hf[1]);
                mma_bf16(sc[2*p],   qh[kt], lf[0], lf[1]);
                mma_bf16(sc[2*p],   ql[kt], hf[0], hf[1]);
                mma_bf16(sc[2*p+1], qh[kt], hf[2], hf[3]);
                mma_bf16(sc[2*p+1], qh[kt], lf[2], lf[3]);
                mma_bf16(sc[2*p+1], ql[kt], hf[2], hf[3]);
            }
        }

        // ---- online softmax (rows g, g+8) ----
        float mx0 = sc[0][0], mx1 = sc[0][2];
#pragma unroll
        for (int nt = 0; nt < 8; nt++) {
            mx0 = fmaxf(mx0, fmaxf(sc[nt][0], sc[nt][1]));
            mx1 = fmaxf(mx1, fmaxf(sc[nt][2], sc[nt][3]));
        }
        mx0 = fmaxf(mx0, __shfl_xor_sync(0xffffffffu, mx0, 1));
        mx0 = fmaxf(mx0, __shfl_xor_sync(0xffffffffu, mx0, 2));
        mx1 = fmaxf(mx1, __shfl_xor_sync(0xffffffffu, mx1, 1));
        mx1 = fmaxf(mx1, __shfl_xor_sync(0xffffffffu, mx1, 2));
        float mn0 = fmaxf(m0r, mx0), mn1 = fmaxf(m1r, mx1);
        float cr0 = __expf(m0r - mn0), cr1 = __expf(m1r - mn1);
        m0r = mn0; m1r = mn1;
        float s0 = 0.f, s1 = 0.f;
#pragma unroll
        for (int nt = 0; nt < 8; nt++) {
            sc[nt][0] = __expf(sc[nt][0] - mn0);
            sc[nt][1] = __expf(sc[nt][1] - mn0);
            sc[nt][2] = __expf(sc[nt][2] - mn1);
            sc[nt][3] = __expf(sc[nt][3] - mn1);
            s0 += sc[nt][0] + sc[nt][1];
            s1 += sc[nt][2] + sc[nt][3];
        }
        s0 += __shfl_xor_sync(0xffffffffu, s0, 1);
        s0 += __shfl_xor_sync(0xffffffffu, s0, 2);
        s1 += __shfl_xor_sync(0xffffffffu, s1, 1);
        s1 += __shfl_xor_sync(0xffffffffu, s1, 2);
        l0r = l0r * cr0 + s0;
        l1r = l1r * cr1 + s1;
#pragma unroll
        for (int nt = 0; nt < 8; nt++) {
            oc[nt][0] *= cr0; oc[nt][1] *= cr0;
            oc[nt][2] *= cr1; oc[nt][3] *= cr1;
        }

        // ---- pack P into PV A-fragments ----
        unsigned pah[4][4], pal[4][4];
#pragma unroll
        for (int kt = 0; kt < 4; kt++) {
            int j0 = 2 * kt, j1 = 2 * kt + 1;
            split_pair(sc[j0][0], sc[j0][1], pah[kt][0], pal[kt][0]);
            split_pair(sc[j0][2], sc[j0][3], pah[kt][1], pal[kt][1]);
            split_pair(sc[j1][0], sc[j1][1], pah[kt][2], pal[kt][2]);
            split_pair(sc[j1][2], sc[j1][3], pah[kt][3], pal[kt][3]);
        }

        // ---- PV ----
#pragma unroll
        for (int p = 0; p < 4; p++) {
#pragma unroll
            for (int kt = 0; kt < 4; kt++) {
                unsigned off = (unsigned)(kt * 16 * KV_LD + p * 16) * 2;
                unsigned hf[4], lf[4];
                ldsm_x4t(hf, vH + off);
                ldsm_x4t(lf, vL + off);
                mma_bf16(oc[2*p],   pah[kt], hf[0], hf[1]);
                mma_bf16(oc[2*p],   pah[kt], lf[0], lf[1]);
                mma_bf16(oc[2*p],   pal[kt], hf[0], hf[1]);
                mma_bf16(oc[2*p+1], pah[kt], hf[2], hf[3]);
                mma_bf16(oc[2*p+1], pah[kt], lf[2], lf[3]);
                mma_bf16(oc[2*p+1], pal[kt], hf[2], hf[3]);
            }
        }
        __syncthreads();
        st ^= 1;
    }

    // ---- epilogue: normalize, split-store O ----
    const float i0 = 1.f / l0r, i1 = 1.f / l1r;
    const int r = q0 + wid * 16 + g;
#pragma unroll
    for (int nt = 0; nt < 8; nt++) {
        int d = nt * 8 + 2 * t;
        unsigned ph, pl;
        split_pair(oc[nt][0] * i0, oc[nt][1] * i0, ph, pl);
        *(unsigned*)&g_Oh[base + (size_t)r * DK_ + d] = ph;
        *(unsigned*)&g_Ol[base + (size_t)r * DK_ + d] = pl;
        split_pair(oc[nt][2] * i1, oc[nt][3] * i1, ph, pl);
        *(unsigned*)&g_Oh[base + (size_t)(r + 8) * DK_ + d] = ph;
        *(unsigned*)&g_Ol[base + (size_t)(r + 8) * DK_ + d] = pl;
    }
}

// ---------------------------------------------------------------------------
extern "C" void kernel_launch(void* const* d_in, const int* in_sizes, int n_in,
                              void* d_out, int out_size)
{
    const float* x  = (const float*)d_in[0];
    const float* WQ = (const float*)d_in[1];
    const float* WK = (const float*)d_in[2];
    const float* WV = (const float*)d_in[3];
    const float* WO = (const float*)d_in[4];
    float* out = (float*)d_out;

    (void)in_sizes; (void)n_in; (void)out_size;

    cudaFuncSetAttribute(qkv_kernel,
        cudaFuncAttributeMaxDynamicSharedMemorySize, GEMM_SMEM_BYTES);
    cudaFuncSetAttribute(out_kernel,
        cudaFuncAttributeMaxDynamicSharedMemorySize, GEMM_SMEM_BYTES);
    cudaFuncSetAttribute(attn_kernel,
        cudaFuncAttributeMaxDynamicSharedMemorySize, ATTN_SMEM_BYTES);

    split_x_kernel<<<M_ * D_ / 8 / 256, 256>>>(x);
    split_wqkv_kernel<<<3 * D_ * D_ / 8 / 256, 256>>>(WQ, WK, WV);
    split_wo_kernel<<<D_ * D_ / 8 / 256, 256>>>(WO);

    qkv_kernel<<<dim3(D_ / 128, M_ / 128, 3), 256, GEMM_SMEM_BYTES>>>();
    attn_kernel<<<dim3(S_ / 128, BH_), 256, ATTN_SMEM_BYTES>>>();
    out_kernel<<<dim3(D_ / 128, M_ / 128), 256, GEMM_SMEM_BYTES>>>(out);
}

// round 11
// speedup vs baseline: 5.5788x; 1.2380x over previous
#include <cuda_runtime.h>
#include <cuda_bf16.h>
#include <cuda_fp16.h>
#include <cstdint>

#define B_  4
#define S_  2048
#define D_  1024
#define H_  16
#define DK_ 64
#define M_  (B_*S_)     // 8192
#define BH_ (B_*H_)     // 64

// bf16 hi/lo operands for the 3-term qkv GEMM
__device__ __nv_bfloat16 g_Xh[M_*D_],   g_Xl[M_*D_];
__device__ __nv_bfloat16 g_Wh[3*D_*D_], g_Wl[3*D_*D_];
// fp16 operands for 2-term attention / out-proj
__device__ __half g_Qh2[BH_*S_*DK_], g_Ql2[BH_*S_*DK_];   // Q split (22-bit)
__device__ __half g_Kf[BH_*S_*DK_];                        // K single
__device__ __half g_Vf[BH_*S_*DK_];                        // V single
__device__ __half g_Oh2[BH_*S_*DK_], g_Ol2[BH_*S_*DK_];   // O split
__device__ __half g_WOf[D_*D_];                            // WO single

// ---------------------------------------------------------------------------
// helpers
// ---------------------------------------------------------------------------
__device__ __forceinline__ unsigned pk_bf16x2(float lo, float hi) {
    unsigned r;
    asm("cvt.rn.bf16x2.f32 %0, %1, %2;" : "=r"(r) : "f"(hi), "f"(lo));
    return r;
}
__device__ __forceinline__ void split_pair(float x, float y, unsigned& h, unsigned& l) {
    h = pk_bf16x2(x, y);
    float hx = __uint_as_float(h << 16);
    float hy = __uint_as_float(h & 0xffff0000u);
    l = pk_bf16x2(x - hx, y - hy);
}
__device__ __forceinline__ unsigned f16pack(float x, float y) {
    __half2 t = __floats2half2_rn(x, y);
    return *reinterpret_cast<unsigned*>(&t);
}
__device__ __forceinline__ void split_f16(float x, float y, unsigned& h, unsigned& l) {
    __half2 t = __floats2half2_rn(x, y);
    float2 b = __half22float2(t);
    h = *reinterpret_cast<unsigned*>(&t);
    __half2 r = __floats2half2_rn(x - b.x, y - b.y);
    l = *reinterpret_cast<unsigned*>(&r);
}
__device__ __forceinline__ unsigned sma(const void* p) {
    return (unsigned)__cvta_generic_to_shared(p);
}
__device__ __forceinline__ void mma_bf16(float* c, const unsigned* a, unsigned b0, unsigned b1) {
    asm("mma.sync.aligned.m16n8k16.row.col.f32.bf16.bf16.f32 "
        "{%0,%1,%2,%3}, {%4,%5,%6,%7}, {%8,%9}, {%0,%1,%2,%3};"
        : "+f"(c[0]), "+f"(c[1]), "+f"(c[2]), "+f"(c[3])
        : "r"(a[0]), "r"(a[1]), "r"(a[2]), "r"(a[3]), "r"(b0), "r"(b1));
}
__device__ __forceinline__ void mma_f16(float* c, const unsigned* a, unsigned b0, unsigned b1) {
    asm("mma.sync.aligned.m16n8k16.row.col.f32.f16.f16.f32 "
        "{%0,%1,%2,%3}, {%4,%5,%6,%7}, {%8,%9}, {%0,%1,%2,%3};"
        : "+f"(c[0]), "+f"(c[1]), "+f"(c[2]), "+f"(c[3])
        : "r"(a[0]), "r"(a[1]), "r"(a[2]), "r"(a[3]), "r"(b0), "r"(b1));
}
__device__ __forceinline__ void ldsm_x4(unsigned* r, unsigned a) {
    asm volatile("ldmatrix.sync.aligned.m8n8.x4.shared.b16 {%0,%1,%2,%3}, [%4];"
                 : "=r"(r[0]), "=r"(r[1]), "=r"(r[2]), "=r"(r[3]) : "r"(a));
}
__device__ __forceinline__ void ldsm_x4t(unsigned* r, unsigned a) {
    asm volatile("ldmatrix.sync.aligned.m8n8.x4.trans.shared.b16 {%0,%1,%2,%3}, [%4];"
                 : "=r"(r[0]), "=r"(r[1]), "=r"(r[2]), "=r"(r[3]) : "r"(a));
}
#define CP16(dst, src) \
    asm volatile("cp.async.cg.shared.global [%0], [%1], 16;" :: "r"(dst), "l"(src) : "memory")
#define CPCOMMIT() asm volatile("cp.async.commit_group;" ::: "memory")
#define CPWAIT1()  asm volatile("cp.async.wait_group 1;" ::: "memory")
#define CPWAIT0()  asm volatile("cp.async.wait_group 0;" ::: "memory")

// ---------------------------------------------------------------------------
// Split kernels
// ---------------------------------------------------------------------------
__global__ __launch_bounds__(256) void split_x_kernel(const float* __restrict__ src) {
    size_t i = (size_t)blockIdx.x * 256 + threadIdx.x;
    float4 v0 = *(const float4*)(src + i * 8);
    float4 v1 = *(const float4*)(src + i * 8 + 4);
    unsigned h0,l0,h1,l1,h2,l2,h3,l3;
    split_pair(v0.x, v0.y, h0, l0); split_pair(v0.z, v0.w, h1, l1);
    split_pair(v1.x, v1.y, h2, l2); split_pair(v1.z, v1.w, h3, l3);
    *(uint4*)(g_Xh + i * 8) = make_uint4(h0, h1, h2, h3);
    *(uint4*)(g_Xl + i * 8) = make_uint4(l0, l1, l2, l3);
}
// W[h][d][dk] (x3) -> [z][k=d][n=h*64+dk]  (bf16 split, k-major rows of n)
__global__ __launch_bounds__(256) void split_wqkv_kernel(
    const float* __restrict__ WQ, const float* __restrict__ WK, const float* __restrict__ WV)
{
    unsigned i = blockIdx.x * 256 + threadIdx.x;
    int o8 = (i & 7) * 8;
    int d  = (i >> 3) & 1023;
    int h  = (i >> 13) & 15;
    int z  = i >> 17;
    const float* src = ((z == 0) ? WQ : (z == 1) ? WK : WV) + ((size_t)h * D_ + d) * DK_ + o8;
    float4 v0 = *(const float4*)(src);
    float4 v1 = *(const float4*)(src + 4);
    unsigned h0,l0,h1,l1,h2,l2,h3,l3;
    split_pair(v0.x, v0.y, h0, l0); split_pair(v0.z, v0.w, h1, l1);
    split_pair(v1.x, v1.y, h2, l2); split_pair(v1.z, v1.w, h3, l3);
    size_t dst = (size_t)z * D_ * D_ + (size_t)d * D_ + h * 64 + o8;
    *(uint4*)(g_Wh + dst) = make_uint4(h0, h1, h2, h3);
    *(uint4*)(g_Wl + dst) = make_uint4(l0, l1, l2, l3);
}
// WO[k][n] -> fp16 single, same layout
__global__ __launch_bounds__(256) void split_wo_kernel(const float* __restrict__ src) {
    size_t i = (size_t)blockIdx.x * 256 + threadIdx.x;
    float4 v0 = *(const float4*)(src + i * 8);
    float4 v1 = *(const float4*)(src + i * 8 + 4);
    *(uint4*)(g_WOf + i * 8) = make_uint4(
        f16pack(v0.x, v0.y), f16pack(v0.z, v0.w),
        f16pack(v1.x, v1.y), f16pack(v1.z, v1.w));
}

// ---------------------------------------------------------------------------
// qkv GEMM (round-6 design: bf16 3-term, cp.async double-buffered, 8 warps
// as 4m x 2n of a 128x128 tile, BK=32). Epilogue emits fp16 Q(split)/K/V.
// ---------------------------------------------------------------------------
#define AS_LD 40
#define BS_LD 136
#define A_SPLIT 5120
#define A_STAGE 10240
#define B_OFF   20480
#define B_SPLIT 4352
#define B_STAGE 8704
#define GEMM_SMEM ((A_STAGE*2 + B_STAGE*2) * 2)   // 75776 B

__global__ __launch_bounds__(256, 2) void qkv_kernel() {
    extern __shared__ __align__(16) char smg[];
    const unsigned sb = sma(smg);
    const int z = blockIdx.z;
    const __nv_bfloat16* Bh = g_Wh + (size_t)z * D_ * D_;
    const __nv_bfloat16* Bl = g_Wl + (size_t)z * D_ * D_;

    const int tid = threadIdx.x, wid = tid >> 5, lane = tid & 31;
    const int wm = wid & 3, wn = wid >> 2;
    const int m0 = blockIdx.y * 128, n0 = blockIdx.x * 128;

    float oc[2][8][4];
#pragma unroll
    for (int a = 0; a < 2; a++)
#pragma unroll
        for (int b = 0; b < 8; b++)
#pragma unroll
            for (int c = 0; c < 4; c++) oc[a][b][c] = 0.f;

    auto stage = [&](int k0, int st) {
#pragma unroll
        for (int u = 0; u < 4; u++) {
            int sp = u >> 1, rem = tid + (u & 1) * 256;
            int row = rem >> 2, ch = (rem & 3) * 8;
            const __nv_bfloat16* s = (sp ? g_Xl : g_Xh) + (size_t)(m0 + row) * D_ + k0 + ch;
            CP16(sb + (st * A_STAGE + sp * A_SPLIT + row * AS_LD + ch) * 2, s);
        }
#pragma unroll
        for (int u = 0; u < 4; u++) {
            int sp = u >> 1, rem = tid + (u & 1) * 256;
            int row = rem >> 4, ch = (rem & 15) * 8;
            const __nv_bfloat16* s = (sp ? Bl : Bh) + (size_t)(k0 + row) * D_ + n0 + ch;
            CP16(sb + (B_OFF + st * B_STAGE + sp * B_SPLIT + row * BS_LD + ch) * 2, s);
        }
    };

    stage(0, 0); CPCOMMIT();

    const int arow = lane & 15, acol = (lane >> 4) * 8;
    const int brow = lane & 15, bcol = (lane & 16) >> 1;

    int st = 0;
    for (int k0 = 0; k0 < D_; k0 += 32) {
        if (k0 + 32 < D_) { stage(k0 + 32, st ^ 1); CPCOMMIT(); CPWAIT1(); }
        else CPWAIT0();
        __syncthreads();
#pragma unroll
        for (int h = 0; h < 2; h++) {
            unsigned ah[2][4], al[2][4];
#pragma unroll
            for (int mi = 0; mi < 2; mi++) {
                unsigned ao = sb + (st * A_STAGE + (wm * 32 + mi * 16 + arow) * AS_LD
                                    + acol + h * 16) * 2;
                ldsm_x4(ah[mi], ao);
                ldsm_x4(al[mi], ao + A_SPLIT * 2);
            }
#pragma unroll
            for (int p = 0; p < 4; p++) {
                unsigned bo = sb + (B_OFF + st * B_STAGE + (h * 16 + brow) * BS_LD
                                    + wn * 64 + p * 16 + bcol) * 2;
                unsigned bhf[4], blf[4];
                ldsm_x4t(bhf, bo);
                ldsm_x4t(blf, bo + B_SPLIT * 2);
#pragma unroll
                for (int mi = 0; mi < 2; mi++) {
                    mma_bf16(oc[mi][2*p],   ah[mi], bhf[0], bhf[1]);
                    mma_bf16(oc[mi][2*p],   ah[mi], blf[0], blf[1]);
                    mma_bf16(oc[mi][2*p],   al[mi], bhf[0], bhf[1]);
                    mma_bf16(oc[mi][2*p+1], ah[mi], bhf[2], bhf[3]);
                    mma_bf16(oc[mi][2*p+1], ah[mi], blf[2], blf[3]);
                    mma_bf16(oc[mi][2*p+1], al[mi], bhf[2], bhf[3]);
                }
            }
        }
        __syncthreads();
        st ^= 1;
    }

    // epilogue: z=0 -> Q split fp16 (scale folded); z=1 -> K fp16; z=2 -> V fp16
    const int g = lane >> 2, t = lane & 3;
#pragma unroll
    for (int mi = 0; mi < 2; mi++)
#pragma unroll
        for (int nt = 0; nt < 8; nt++) {
            int n = n0 + wn * 64 + nt * 8 + 2 * t;
            int hh = n >> 6, d = n & 63;
            int m = m0 + wm * 32 + mi * 16 + g;
            int b = m >> 11, s = m & (S_ - 1);
            size_t idx = ((size_t)(b * H_ + hh) * S_ + s) * DK_ + d;
            if (z == 0) {
                unsigned ph, pl;
                split_f16(oc[mi][nt][0] * 0.125f, oc[mi][nt][1] * 0.125f, ph, pl);
                *(unsigned*)&g_Qh2[idx] = ph;  *(unsigned*)&g_Ql2[idx] = pl;
                split_f16(oc[mi][nt][2] * 0.125f, oc[mi][nt][3] * 0.125f, ph, pl);
                *(unsigned*)&g_Qh2[idx + 8 * DK_] = ph;
                *(unsigned*)&g_Ql2[idx + 8 * DK_] = pl;
            } else {
                __half* Kv = (z == 1) ? g_Kf : g_Vf;
                *(unsigned*)&Kv[idx]           = f16pack(oc[mi][nt][0], oc[mi][nt][1]);
                *(unsigned*)&Kv[idx + 8 * DK_] = f16pack(oc[mi][nt][2], oc[mi][nt][3]);
            }
        }
}

// ---------------------------------------------------------------------------
// Flash attention: fp16 2-term. K and V are SINGLE arrays (half the smem,
// half the LDSM/staging of round 6); Q and P split fp16.
// ---------------------------------------------------------------------------
#define KV_LD 72
#define KV_ARR_B  (64 * KV_LD * 2)        // 9216 B per array
#define KV_STAGE_B (2 * KV_ARR_B)         // 18432 B (K + V)
#define ATTN_SMEM (2 * KV_STAGE_B)        // 36864 B

__global__ __launch_bounds__(256) void attn_kernel() {
    extern __shared__ __align__(16) char smg[];
    __half* smh = (__half*)smg;
    const unsigned sb = sma(smg);
    const int tid = threadIdx.x, wid = tid >> 5, lane = tid & 31;
    const int g = lane >> 2, t = lane & 3;
    const int bh = blockIdx.y, q0 = blockIdx.x * 128;
    const size_t base = (size_t)bh * S_ * DK_;

    // hoist Q fragments (hi then lo) via smem
    unsigned qh[4][4], ql[4][4];
#pragma unroll
    for (int pass = 0; pass < 2; pass++) {
        const __half* src = pass ? g_Ql2 : g_Qh2;
        for (int i = tid; i < 1024; i += 256) {
            int row = i >> 3, c8 = (i & 7) * 8;
            *(uint4*)&smh[row * KV_LD + c8] =
                *(const uint4*)&src[base + (size_t)(q0 + row) * DK_ + c8];
        }
        __syncthreads();
        unsigned ad = sb + ((wid * 16 + (lane & 15)) * KV_LD + (lane >> 4) * 8) * 2;
#pragma unroll
        for (int kt = 0; kt < 4; kt++)
            ldsm_x4(pass ? ql[kt] : qh[kt], ad + kt * 32);
        __syncthreads();
    }

    float oc[8][4];
#pragma unroll
    for (int i = 0; i < 8; i++)
#pragma unroll
        for (int j = 0; j < 4; j++) oc[i][j] = 0.f;
    float m0r = -1e30f, m1r = -1e30f, l0r = 0.f, l1r = 0.f;

    const unsigned kb = (((lane & 7) + ((lane & 16) >> 1)) * KV_LD + (lane & 8)) * 2;
    const unsigned vb = ((lane & 15) * KV_LD + ((lane & 16) >> 1)) * 2;

    auto stage = [&](int kv0, int st) {
#pragma unroll
        for (int u = 0; u < 4; u++) {
            int arr = u >> 1, rem = tid + (u & 1) * 256;
            int row = rem >> 3, ch = (rem & 7) * 8;
            const __half* s = (arr == 0 ? g_Kf : g_Vf)
                + base + (size_t)(kv0 + row) * DK_ + ch;
            CP16(sb + st * KV_STAGE_B + arr * KV_ARR_B + (row * KV_LD + ch) * 2, s);
        }
    };

    stage(0, 0); CPCOMMIT();

    int st = 0;
    for (int kv0 = 0; kv0 < S_; kv0 += 64) {
        if (kv0 + 64 < S_) { stage(kv0 + 64, st ^ 1); CPCOMMIT(); CPWAIT1(); }
        else CPWAIT0();
        __syncthreads();

        const unsigned kK = sb + st * KV_STAGE_B + kb;
        const unsigned vV = sb + st * KV_STAGE_B + KV_ARR_B + vb;

        // ---- scores: 2 terms (Q split x K single) ----
        float sc[8][4];
#pragma unroll
        for (int i = 0; i < 8; i++)
#pragma unroll
            for (int j = 0; j < 4; j++) sc[i][j] = 0.f;
#pragma unroll
        for (int p = 0; p < 4; p++) {
#pragma unroll
            for (int kt = 0; kt < 4; kt++) {
                unsigned off = (unsigned)(p * 16 * KV_LD + kt * 16) * 2;
                unsigned kf[4];
                ldsm_x4(kf, kK + off);
                mma_f16(sc[2*p],   qh[kt], kf[0], kf[1]);
                mma_f16(sc[2*p],   ql[kt], kf[0], kf[1]);
                mma_f16(sc[2*p+1], qh[kt], kf[2], kf[3]);
                mma_f16(sc[2*p+1], ql[kt], kf[2], kf[3]);
            }
        }

        // ---- online softmax (rows g, g+8) ----
        float mx0 = sc[0][0], mx1 = sc[0][2];
#pragma unroll
        for (int nt = 0; nt < 8; nt++) {
            mx0 = fmaxf(mx0, fmaxf(sc[nt][0], sc[nt][1]));
            mx1 = fmaxf(mx1, fmaxf(sc[nt][2], sc[nt][3]));
        }
        mx0 = fmaxf(mx0, __shfl_xor_sync(0xffffffffu, mx0, 1));
        mx0 = fmaxf(mx0, __shfl_xor_sync(0xffffffffu, mx0, 2));
        mx1 = fmaxf(mx1, __shfl_xor_sync(0xffffffffu, mx1, 1));
        mx1 = fmaxf(mx1, __shfl_xor_sync(0xffffffffu, mx1, 2));
        float mn0 = fmaxf(m0r, mx0), mn1 = fmaxf(m1r, mx1);
        float cr0 = __expf(m0r - mn0), cr1 = __expf(m1r - mn1);
        m0r = mn0; m1r = mn1;
        float s0 = 0.f, s1 = 0.f;
#pragma unroll
        for (int nt = 0; nt < 8; nt++) {
            sc[nt][0] = __expf(sc[nt][0] - mn0);
            sc[nt][1] = __expf(sc[nt][1] - mn0);
            sc[nt][2] = __expf(sc[nt][2] - mn1);
            sc[nt][3] = __expf(sc[nt][3] - mn1);
            s0 += sc[nt][0] + sc[nt][1];
            s1 += sc[nt][2] + sc[nt][3];
        }
        s0 += __shfl_xor_sync(0xffffffffu, s0, 1);
        s0 += __shfl_xor_sync(0xffffffffu, s0, 2);
        s1 += __shfl_xor_sync(0xffffffffu, s1, 1);
        s1 += __shfl_xor_sync(0xffffffffu, s1, 2);
        l0r = l0r * cr0 + s0;
        l1r = l1r * cr1 + s1;
#pragma unroll
        for (int nt = 0; nt < 8; nt++) {
            oc[nt][0] *= cr0; oc[nt][1] *= cr0;
            oc[nt][2] *= cr1; oc[nt][3] *= cr1;
        }

        // ---- pack P into fp16 split A-fragments ----
        unsigned pah[4][4], pal[4][4];
#pragma unroll
        for (int kt = 0; kt < 4; kt++) {
            int j0 = 2 * kt, j1 = 2 * kt + 1;
            split_f16(sc[j0][0], sc[j0][1], pah[kt][0], pal[kt][0]);
            split_f16(sc[j0][2], sc[j0][3], pah[kt][1], pal[kt][1]);
            split_f16(sc[j1][0], sc[j1][1], pah[kt][2], pal[kt][2]);
            split_f16(sc[j1][2], sc[j1][3], pah[kt][3], pal[kt][3]);
        }

        // ---- PV: 2 terms (P split x V single) ----
#pragma unroll
        for (int p = 0; p < 4; p++) {
#pragma unroll
            for (int kt = 0; kt < 4; kt++) {
                unsigned off = (unsigned)(kt * 16 * KV_LD + p * 16) * 2;
                unsigned vf[4];
                ldsm_x4t(vf, vV + off);
                mma_f16(oc[2*p],   pah[kt], vf[0], vf[1]);
                mma_f16(oc[2*p],   pal[kt], vf[0], vf[1]);
                mma_f16(oc[2*p+1], pah[kt], vf[2], vf[3]);
                mma_f16(oc[2*p+1], pal[kt], vf[2], vf[3]);
            }
        }
        __syncthreads();
        st ^= 1;
    }

    // epilogue: normalize, split-store O (fp16 pairs)
    const float i0 = 1.f / l0r, i1 = 1.f / l1r;
    const int r = q0 + wid * 16 + g;
#pragma unroll
    for (int nt = 0; nt < 8; nt++) {
        int d = nt * 8 + 2 * t;
        unsigned ph, pl;
        split_f16(oc[nt][0] * i0, oc[nt][1] * i0, ph, pl);
        *(unsigned*)&g_Oh2[base + (size_t)r * DK_ + d] = ph;
        *(unsigned*)&g_Ol2[base + (size_t)r * DK_ + d] = pl;
        split_f16(oc[nt][2] * i1, oc[nt][3] * i1, ph, pl);
        *(unsigned*)&g_Oh2[base + (size_t)(r + 8) * DK_ + d] = ph;
        *(unsigned*)&g_Ol2[base + (size_t)(r + 8) * DK_ + d] = pl;
    }
}

// ---------------------------------------------------------------------------
// Output projection: fp16 2-term (O split x WO single). fp32 out.
// ---------------------------------------------------------------------------
#define OB_OFF   (2 * A_STAGE)            // elems; B region after 2 A stages
#define OB_STAGE B_SPLIT                  // 4352 elems (single array)
#define OUT_SMEM ((2 * A_STAGE + 2 * OB_STAGE) * 2)   // 58368 B

__global__ __launch_bounds__(256, 2) void out_kernel(float* __restrict__ Out) {
    extern __shared__ __align__(16) char smg[];
    const unsigned sb = sma(smg);
    const int tid = threadIdx.x, wid = tid >> 5, lane = tid & 31;
    const int wm = wid & 3, wn = wid >> 2;
    const int m0 = blockIdx.y * 128, n0 = blockIdx.x * 128;

    float oc[2][8][4];
#pragma unroll
    for (int a = 0; a < 2; a++)
#pragma unroll
        for (int b = 0; b < 8; b++)
#pragma unroll
            for (int c = 0; c < 4; c++) oc[a][b][c] = 0.f;

    auto stage = [&](int k0, int st) {
#pragma unroll
        for (int u = 0; u < 4; u++) {             // A: O hi/lo
            int sp = u >> 1, rem = tid + (u & 1) * 256;
            int row = rem >> 2, ch = (rem & 3) * 8;
            int m = m0 + row, b = m >> 11, s = m & (S_ - 1);
            const __half* src = (sp ? g_Ol2 : g_Oh2)
                + ((size_t)(b * H_ + (k0 >> 6)) * S_ + s) * DK_ + (k0 & 63) + ch;
            CP16(sb + (st * A_STAGE + sp * A_SPLIT + row * AS_LD + ch) * 2, src);
        }
#pragma unroll
        for (int u = 0; u < 2; u++) {             // B: WO single
            int rem = tid + u * 256;
            int row = rem >> 4, ch = (rem & 15) * 8;
            const __half* src = g_WOf + (size_t)(k0 + row) * D_ + n0 + ch;
            CP16(sb + (OB_OFF + st * OB_STAGE + row * BS_LD + ch) * 2, src);
        }
    };

    stage(0, 0); CPCOMMIT();

    const int arow = lane & 15, acol = (lane >> 4) * 8;
    const int brow = lane & 15, bcol = (lane & 16) >> 1;

    int st = 0;
    for (int k0 = 0; k0 < D_; k0 += 32) {
        if (k0 + 32 < D_) { stage(k0 + 32, st ^ 1); CPCOMMIT(); CPWAIT1(); }
        else CPWAIT0();
        __syncthreads();
#pragma unroll
        for (int h = 0; h < 2; h++) {
            unsigned ah[2][4], al[2][4];
#pragma unroll
            for (int mi = 0; mi < 2; mi++) {
                unsigned ao = sb + (st * A_STAGE + (wm * 32 + mi * 16 + arow) * AS_LD
                                    + acol + h * 16) * 2;
                ldsm_x4(ah[mi], ao);
                ldsm_x4(al[mi], ao + A_SPLIT * 2);
            }
#pragma unroll
            for (int p = 0; p < 4; p++) {
                unsigned bo = sb + (OB_OFF + st * OB_STAGE + (h * 16 + brow) * BS_LD
                                    + wn * 64 + p * 16 + bcol) * 2;
                unsigned bf[4];
                ldsm_x4t(bf, bo);
#pragma unroll
                for (int mi = 0; mi < 2; mi++) {
                    mma_f16(oc[mi][2*p],   ah[mi], bf[0], bf[1]);
                    mma_f16(oc[mi][2*p],   al[mi], bf[0], bf[1]);
                    mma_f16(oc[mi][2*p+1], ah[mi], bf[2], bf[3]);
                    mma_f16(oc[mi][2*p+1], al[mi], bf[2], bf[3]);
                }
            }
        }
        __syncthreads();
        st ^= 1;
    }

    const int g = lane >> 2, t = lane & 3;
#pragma unroll
    for (int mi = 0; mi < 2; mi++)
#pragma unroll
        for (int nt = 0; nt < 8; nt++) {
            int n = n0 + wn * 64 + nt * 8 + 2 * t;
            int m = m0 + wm * 32 + mi * 16 + g;
            *(float2*)&Out[(size_t)m * D_ + n] = make_float2(oc[mi][nt][0], oc[mi][nt][1]);
            *(float2*)&Out[(size_t)(m + 8) * D_ + n] = make_float2(oc[mi][nt][2], oc[mi][nt][3]);
        }
}

// ---------------------------------------------------------------------------
extern "C" void kernel_launch(void* const* d_in, const int* in_sizes, int n_in,
                              void* d_out, int out_size)
{
    const float* x  = (const float*)d_in[0];
    const float* WQ = (const float*)d_in[1];
    const float* WK = (const float*)d_in[2];
    const float* WV = (const float*)d_in[3];
    const float* WO = (const float*)d_in[4];
    float* out = (float*)d_out;

    (void)in_sizes; (void)n_in; (void)out_size;

    cudaFuncSetAttribute(qkv_kernel,
        cudaFuncAttributeMaxDynamicSharedMemorySize, GEMM_SMEM);
    cudaFuncSetAttribute(out_kernel,
        cudaFuncAttributeMaxDynamicSharedMemorySize, OUT_SMEM);
    cudaFuncSetAttribute(attn_kernel,
        cudaFuncAttributeMaxDynamicSharedMemorySize, ATTN_SMEM);

    split_x_kernel<<<M_ * D_ / 8 / 256, 256>>>(x);
    split_wqkv_kernel<<<3 * D_ * D_ / 8 / 256, 256>>>(WQ, WK, WV);
    split_wo_kernel<<<D_ * D_ / 8 / 256, 256>>>(WO);

    qkv_kernel<<<dim3(D_ / 128, M_ / 128, 3), 256, GEMM_SMEM>>>();
    attn_kernel<<<dim3(S_ / 128, BH_), 256, ATTN_SMEM>>>();
    out_kernel<<<dim3(D_ / 128, M_ / 128), 256, OUT_SMEM>>>(out);
}

// round 13
// speedup vs baseline: 6.9673x; 1.2489x over previous
#include <cuda_runtime.h>
#include <cuda_fp16.h>
#include <cstdint>

#define B_  4
#define S_  2048
#define D_  1024
#define H_  16
#define DK_ 64
#define M_  (B_*S_)     // 8192
#define BH_ (B_*H_)     // 64

// fp16 operands (all split/pack done once by split kernels)
__device__ __half g_Xh2[M_*D_], g_Xl2[M_*D_];             // X split (22-bit)
__device__ __half g_Wf[3*D_*D_];                           // W qkv single, [z][k][n]
__device__ __half g_Qh2[BH_*S_*DK_], g_Ql2[BH_*S_*DK_];   // Q split
__device__ __half g_Kf[BH_*S_*DK_];                        // K single
__device__ __half g_Vf[BH_*S_*DK_];                        // V single
__device__ __half g_Oh2[BH_*S_*DK_], g_Ol2[BH_*S_*DK_];   // O split
__device__ __half g_WOf[D_*D_];                            // WO single

// ---------------------------------------------------------------------------
// helpers
// ---------------------------------------------------------------------------
__device__ __forceinline__ unsigned f16pack(float x, float y) {
    __half2 t = __floats2half2_rn(x, y);
    return *reinterpret_cast<unsigned*>(&t);
}
__device__ __forceinline__ void split_f16(float x, float y, unsigned& h, unsigned& l) {
    __half2 t = __floats2half2_rn(x, y);
    float2 b = __half22float2(t);
    h = *reinterpret_cast<unsigned*>(&t);
    __half2 r = __floats2half2_rn(x - b.x, y - b.y);
    l = *reinterpret_cast<unsigned*>(&r);
}
__device__ __forceinline__ unsigned sma(const void* p) {
    return (unsigned)__cvta_generic_to_shared(p);
}
__device__ __forceinline__ void mma_f16(float* c, const unsigned* a, unsigned b0, unsigned b1) {
    asm("mma.sync.aligned.m16n8k16.row.col.f32.f16.f16.f32 "
        "{%0,%1,%2,%3}, {%4,%5,%6,%7}, {%8,%9}, {%0,%1,%2,%3};"
        : "+f"(c[0]), "+f"(c[1]), "+f"(c[2]), "+f"(c[3])
        : "r"(a[0]), "r"(a[1]), "r"(a[2]), "r"(a[3]), "r"(b0), "r"(b1));
}
__device__ __forceinline__ void ldsm_x4(unsigned* r, unsigned a) {
    asm volatile("ldmatrix.sync.aligned.m8n8.x4.shared.b16 {%0,%1,%2,%3}, [%4];"
                 : "=r"(r[0]), "=r"(r[1]), "=r"(r[2]), "=r"(r[3]) : "r"(a));
}
__device__ __forceinline__ void ldsm_x4t(unsigned* r, unsigned a) {
    asm volatile("ldmatrix.sync.aligned.m8n8.x4.trans.shared.b16 {%0,%1,%2,%3}, [%4];"
                 : "=r"(r[0]), "=r"(r[1]), "=r"(r[2]), "=r"(r[3]) : "r"(a));
}
#define CP16(dst, src) \
    asm volatile("cp.async.cg.shared.global [%0], [%1], 16;" :: "r"(dst), "l"(src) : "memory")
#define CPCOMMIT() asm volatile("cp.async.commit_group;" ::: "memory")
#define CPWAIT1()  asm volatile("cp.async.wait_group 1;" ::: "memory")
#define CPWAIT0()  asm volatile("cp.async.wait_group 0;" ::: "memory")

// ---------------------------------------------------------------------------
// Split kernels
// ---------------------------------------------------------------------------
__global__ __launch_bounds__(256) void split_x_kernel(const float* __restrict__ src) {
    size_t i = (size_t)blockIdx.x * 256 + threadIdx.x;
    float4 v0 = *(const float4*)(src + i * 8);
    float4 v1 = *(const float4*)(src + i * 8 + 4);
    unsigned h0,l0,h1,l1,h2,l2,h3,l3;
    split_f16(v0.x, v0.y, h0, l0); split_f16(v0.z, v0.w, h1, l1);
    split_f16(v1.x, v1.y, h2, l2); split_f16(v1.z, v1.w, h3, l3);
    *(uint4*)(g_Xh2 + i * 8) = make_uint4(h0, h1, h2, h3);
    *(uint4*)(g_Xl2 + i * 8) = make_uint4(l0, l1, l2, l3);
}
// W[h][d][dk] (x3) -> fp16 single [z][k=d][n=h*64+dk]
__global__ __launch_bounds__(256) void split_wqkv_kernel(
    const float* __restrict__ WQ, const float* __restrict__ WK, const float* __restrict__ WV)
{
    unsigned i = blockIdx.x * 256 + threadIdx.x;
    int o8 = (i & 7) * 8;
    int d  = (i >> 3) & 1023;
    int h  = (i >> 13) & 15;
    int z  = i >> 17;
    const float* src = ((z == 0) ? WQ : (z == 1) ? WK : WV) + ((size_t)h * D_ + d) * DK_ + o8;
    float4 v0 = *(const float4*)(src);
    float4 v1 = *(const float4*)(src + 4);
    size_t dst = (size_t)z * D_ * D_ + (size_t)d * D_ + h * 64 + o8;
    *(uint4*)(g_Wf + dst) = make_uint4(
        f16pack(v0.x, v0.y), f16pack(v0.z, v0.w),
        f16pack(v1.x, v1.y), f16pack(v1.z, v1.w));
}
__global__ __launch_bounds__(256) void split_wo_kernel(const float* __restrict__ src) {
    size_t i = (size_t)blockIdx.x * 256 + threadIdx.x;
    float4 v0 = *(const float4*)(src + i * 8);
    float4 v1 = *(const float4*)(src + i * 8 + 4);
    *(uint4*)(g_WOf + i * 8) = make_uint4(
        f16pack(v0.x, v0.y), f16pack(v0.z, v0.w),
        f16pack(v1.x, v1.y), f16pack(v1.z, v1.w));
}

// ---------------------------------------------------------------------------
// GEMM tiling (both projections): 128x128 tile, 8 warps 4m x 2n, BK=32,
// A = split fp16 (2 arrays), B = single fp16, cp.async double-buffered.
// ---------------------------------------------------------------------------
#define AS_LD 40
#define BS_LD 136
#define A_SPLIT 5120
#define A_STAGE 10240
#define GB_OFF   (2 * A_STAGE)         // elems
#define GB_STAGE 4352                  // 32*136 elems (single array)
#define GEMM_SMEM ((2 * A_STAGE + 2 * GB_STAGE) * 2)   // 58368 B

// MODE 0 = qkv (A from X split, B from g_Wf[z], epilogue -> Q/K/V fp16)
// MODE 1 = out (A from O split, B from g_WOf, epilogue -> fp32 out)
template<int MODE>
__global__ __launch_bounds__(256, 2) void gemm_kernel(float* __restrict__ Out) {
    extern __shared__ __align__(16) char smg[];
    const unsigned sb = sma(smg);
    const int z = (MODE == 0) ? blockIdx.z : 0;
    const __half* Bsrc = (MODE == 0) ? g_Wf + (size_t)z * D_ * D_ : g_WOf;

    const int tid = threadIdx.x, wid = tid >> 5, lane = tid & 31;
    const int wm = wid & 3, wn = wid >> 2;
    const int m0 = blockIdx.y * 128, n0 = blockIdx.x * 128;

    float oc[2][8][4];
#pragma unroll
    for (int a = 0; a < 2; a++)
#pragma unroll
        for (int b = 0; b < 8; b++)
#pragma unroll
            for (int c = 0; c < 4; c++) oc[a][b][c] = 0.f;

    auto stage = [&](int k0, int st) {
#pragma unroll
        for (int u = 0; u < 4; u++) {             // A hi/lo: 128x32
            int sp = u >> 1, rem = tid + (u & 1) * 256;
            int row = rem >> 2, ch = (rem & 3) * 8;
            const __half* src;
            if (MODE == 0) {
                src = (sp ? g_Xl2 : g_Xh2) + (size_t)(m0 + row) * D_ + k0 + ch;
            } else {
                int m = m0 + row, b = m >> 11, s = m & (S_ - 1);
                src = (sp ? g_Ol2 : g_Oh2)
                    + ((size_t)(b * H_ + (k0 >> 6)) * S_ + s) * DK_ + (k0 & 63) + ch;
            }
            CP16(sb + (st * A_STAGE + sp * A_SPLIT + row * AS_LD + ch) * 2, src);
        }
#pragma unroll
        for (int u = 0; u < 2; u++) {             // B single: 32x128
            int rem = tid + u * 256;
            int row = rem >> 4, ch = (rem & 15) * 8;
            const __half* src = Bsrc + (size_t)(k0 + row) * D_ + n0 + ch;
            CP16(sb + (GB_OFF + st * GB_STAGE + row * BS_LD + ch) * 2, src);
        }
    };

    stage(0, 0); CPCOMMIT();

    const int arow = lane & 15, acol = (lane >> 4) * 8;
    const int brow = lane & 15, bcol = (lane & 16) >> 1;

    int st = 0;
    for (int k0 = 0; k0 < D_; k0 += 32) {
        if (k0 + 32 < D_) { stage(k0 + 32, st ^ 1); CPCOMMIT(); CPWAIT1(); }
        else CPWAIT0();
        __syncthreads();
#pragma unroll
        for (int h = 0; h < 2; h++) {
            unsigned ah[2][4], al[2][4];
#pragma unroll
            for (int mi = 0; mi < 2; mi++) {
                unsigned ao = sb + (st * A_STAGE + (wm * 32 + mi * 16 + arow) * AS_LD
                                    + acol + h * 16) * 2;
                ldsm_x4(ah[mi], ao);
                ldsm_x4(al[mi], ao + A_SPLIT * 2);
            }
#pragma unroll
            for (int p = 0; p < 4; p++) {
                unsigned bo = sb + (GB_OFF + st * GB_STAGE + (h * 16 + brow) * BS_LD
                                    + wn * 64 + p * 16 + bcol) * 2;
                unsigned bf[4];
                ldsm_x4t(bf, bo);
#pragma unroll
                for (int mi = 0; mi < 2; mi++) {
                    mma_f16(oc[mi][2*p],   ah[mi], bf[0], bf[1]);
                    mma_f16(oc[mi][2*p],   al[mi], bf[0], bf[1]);
                    mma_f16(oc[mi][2*p+1], ah[mi], bf[2], bf[3]);
                    mma_f16(oc[mi][2*p+1], al[mi], bf[2], bf[3]);
                }
            }
        }
        __syncthreads();
        st ^= 1;
    }

    const int g = lane >> 2, t = lane & 3;
#pragma unroll
    for (int mi = 0; mi < 2; mi++)
#pragma unroll
        for (int nt = 0; nt < 8; nt++) {
            int n = n0 + wn * 64 + nt * 8 + 2 * t;
            int m = m0 + wm * 32 + mi * 16 + g;
            if (MODE == 0) {
                int hh = n >> 6, d = n & 63;
                int b = m >> 11, s = m & (S_ - 1);
                size_t idx = ((size_t)(b * H_ + hh) * S_ + s) * DK_ + d;
                if (z == 0) {
                    unsigned ph, pl;
                    split_f16(oc[mi][nt][0] * 0.125f, oc[mi][nt][1] * 0.125f, ph, pl);
                    *(unsigned*)&g_Qh2[idx] = ph;  *(unsigned*)&g_Ql2[idx] = pl;
                    split_f16(oc[mi][nt][2] * 0.125f, oc[mi][nt][3] * 0.125f, ph, pl);
                    *(unsigned*)&g_Qh2[idx + 8 * DK_] = ph;
                    *(unsigned*)&g_Ql2[idx + 8 * DK_] = pl;
                } else {
                    __half* Kv = (z == 1) ? g_Kf : g_Vf;
                    *(unsigned*)&Kv[idx]           = f16pack(oc[mi][nt][0], oc[mi][nt][1]);
                    *(unsigned*)&Kv[idx + 8 * DK_] = f16pack(oc[mi][nt][2], oc[mi][nt][3]);
                }
            } else {
                *(float2*)&Out[(size_t)m * D_ + n] =
                    make_float2(oc[mi][nt][0], oc[mi][nt][1]);
                *(float2*)&Out[(size_t)(m + 8) * D_ + n] =
                    make_float2(oc[mi][nt][2], oc[mi][nt][3]);
            }
        }
}

// ---------------------------------------------------------------------------
// Flash attention: scores 2-term (Q split x K single), PV 1-term (P single
// x V single). cp.async double-buffered KV (single arrays).
// ---------------------------------------------------------------------------
#define KV_LD 72
#define KV_ARR_B  (64 * KV_LD * 2)
#define KV_STAGE_B (2 * KV_ARR_B)
#define ATTN_SMEM (2 * KV_STAGE_B)        // 36864 B

__global__ __launch_bounds__(256) void attn_kernel() {
    extern __shared__ __align__(16) char smg[];
    __half* smh = (__half*)smg;
    const unsigned sb = sma(smg);
    const int tid = threadIdx.x, wid = tid >> 5, lane = tid & 31;
    const int g = lane >> 2, t = lane & 3;
    const int bh = blockIdx.y, q0 = blockIdx.x * 128;
    const size_t base = (size_t)bh * S_ * DK_;

    unsigned qh[4][4], ql[4][4];
#pragma unroll
    for (int pass = 0; pass < 2; pass++) {
        const __half* src = pass ? g_Ql2 : g_Qh2;
        for (int i = tid; i < 1024; i += 256) {
            int row = i >> 3, c8 = (i & 7) * 8;
            *(uint4*)&smh[row * KV_LD + c8] =
                *(const uint4*)&src[base + (size_t)(q0 + row) * DK_ + c8];
        }
        __syncthreads();
        unsigned ad = sb + ((wid * 16 + (lane & 15)) * KV_LD + (lane >> 4) * 8) * 2;
#pragma unroll
        for (int kt = 0; kt < 4; kt++)
            ldsm_x4(pass ? ql[kt] : qh[kt], ad + kt * 32);
        __syncthreads();
    }

    float oc[8][4];
#pragma unroll
    for (int i = 0; i < 8; i++)
#pragma unroll
        for (int j = 0; j < 4; j++) oc[i][j] = 0.f;
    float m0r = -1e30f, m1r = -1e30f, l0r = 0.f, l1r = 0.f;

    const unsigned kb = (((lane & 7) + ((lane & 16) >> 1)) * KV_LD + (lane & 8)) * 2;
    const unsigned vb = ((lane & 15) * KV_LD + ((lane & 16) >> 1)) * 2;

    auto stage = [&](int kv0, int st) {
#pragma unroll
        for (int u = 0; u < 4; u++) {
            int arr = u >> 1, rem = tid + (u & 1) * 256;
            int row = rem >> 3, ch = (rem & 7) * 8;
            const __half* s = (arr == 0 ? g_Kf : g_Vf)
                + base + (size_t)(kv0 + row) * DK_ + ch;
            CP16(sb + st * KV_STAGE_B + arr * KV_ARR_B + (row * KV_LD + ch) * 2, s);
        }
    };

    stage(0, 0); CPCOMMIT();

    int st = 0;
    for (int kv0 = 0; kv0 < S_; kv0 += 64) {
        if (kv0 + 64 < S_) { stage(kv0 + 64, st ^ 1); CPCOMMIT(); CPWAIT1(); }
        else CPWAIT0();
        __syncthreads();

        const unsigned kK = sb + st * KV_STAGE_B + kb;
        const unsigned vV = sb + st * KV_STAGE_B + KV_ARR_B + vb;

        // ---- scores: Q split x K single ----
        float sc[8][4];
#pragma unroll
        for (int i = 0; i < 8; i++)
#pragma unroll
            for (int j = 0; j < 4; j++) sc[i][j] = 0.f;
#pragma unroll
        for (int p = 0; p < 4; p++) {
#pragma unroll
            for (int kt = 0; kt < 4; kt++) {
                unsigned off = (unsigned)(p * 16 * KV_LD + kt * 16) * 2;
                unsigned kf[4];
                ldsm_x4(kf, kK + off);
                mma_f16(sc[2*p],   qh[kt], kf[0], kf[1]);
                mma_f16(sc[2*p],   ql[kt], kf[0], kf[1]);
                mma_f16(sc[2*p+1], qh[kt], kf[2], kf[3]);
                mma_f16(sc[2*p+1], ql[kt], kf[2], kf[3]);
            }
        }

        // ---- online softmax (rows g, g+8) ----
        float mx0 = sc[0][0], mx1 = sc[0][2];
#pragma unroll
        for (int nt = 0; nt < 8; nt++) {
            mx0 = fmaxf(mx0, fmaxf(sc[nt][0], sc[nt][1]));
            mx1 = fmaxf(mx1, fmaxf(sc[nt][2], sc[nt][3]));
        }
        mx0 = fmaxf(mx0, __shfl_xor_sync(0xffffffffu, mx0, 1));
        mx0 = fmaxf(mx0, __shfl_xor_sync(0xffffffffu, mx0, 2));
        mx1 = fmaxf(mx1, __shfl_xor_sync(0xffffffffu, mx1, 1));
        mx1 = fmaxf(mx1, __shfl_xor_sync(0xffffffffu, mx1, 2));
        float mn0 = fmaxf(m0r, mx0), mn1 = fmaxf(m1r, mx1);
        float cr0 = __expf(m0r - mn0), cr1 = __expf(m1r - mn1);
        m0r = mn0; m1r = mn1;
        float s0 = 0.f, s1 = 0.f;
#pragma unroll
        for (int nt = 0; nt < 8; nt++) {
            sc[nt][0] = __expf(sc[nt][0] - mn0);
            sc[nt][1] = __expf(sc[nt][1] - mn0);
            sc[nt][2] = __expf(sc[nt][2] - mn1);
            sc[nt][3] = __expf(sc[nt][3] - mn1);
            s0 += sc[nt][0] + sc[nt][1];
            s1 += sc[nt][2] + sc[nt][3];
        }
        s0 += __shfl_xor_sync(0xffffffffu, s0, 1);
        s0 += __shfl_xor_sync(0xffffffffu, s0, 2);
        s1 += __shfl_xor_sync(0xffffffffu, s1, 1);
        s1 += __shfl_xor_sync(0xffffffffu, s1, 2);
        l0r = l0r * cr0 + s0;
        l1r = l1r * cr1 + s1;
#pragma unroll
        for (int nt = 0; nt < 8; nt++) {
            oc[nt][0] *= cr0; oc[nt][1] *= cr0;
            oc[nt][2] *= cr1; oc[nt][3] *= cr1;
        }

        // ---- pack P single fp16 ----
        unsigned pa[4][4];
#pragma unroll
        for (int kt = 0; kt < 4; kt++) {
            int j0 = 2 * kt, j1 = 2 * kt + 1;
            pa[kt][0] = f16pack(sc[j0][0], sc[j0][1]);
            pa[kt][1] = f16pack(sc[j0][2], sc[j0][3]);
            pa[kt][2] = f16pack(sc[j1][0], sc[j1][1]);
            pa[kt][3] = f16pack(sc[j1][2], sc[j1][3]);
        }

        // ---- PV: 1 term (P single x V single) ----
#pragma unroll
        for (int p = 0; p < 4; p++) {
#pragma unroll
            for (int kt = 0; kt < 4; kt++) {
                unsigned off = (unsigned)(kt * 16 * KV_LD + p * 16) * 2;
                unsigned vf[4];
                ldsm_x4t(vf, vV + off);
                mma_f16(oc[2*p],   pa[kt], vf[0], vf[1]);
                mma_f16(oc[2*p+1], pa[kt], vf[2], vf[3]);
            }
        }
        __syncthreads();
        st ^= 1;
    }

    // epilogue: normalize, split-store O
    const float i0 = 1.f / l0r, i1 = 1.f / l1r;
    const int r = q0 + wid * 16 + g;
#pragma unroll
    for (int nt = 0; nt < 8; nt++) {
        int d = nt * 8 + 2 * t;
        unsigned ph, pl;
        split_f16(oc[nt][0] * i0, oc[nt][1] * i0, ph, pl);
        *(unsigned*)&g_Oh2[base + (size_t)r * DK_ + d] = ph;
        *(unsigned*)&g_Ol2[base + (size_t)r * DK_ + d] = pl;
        split_f16(oc[nt][2] * i1, oc[nt][3] * i1, ph, pl);
        *(unsigned*)&g_Oh2[base + (size_t)(r + 8) * DK_ + d] = ph;
        *(unsigned*)&g_Ol2[base + (size_t)(r + 8) * DK_ + d] = pl;
    }
}

// ---------------------------------------------------------------------------
extern "C" void kernel_launch(void* const* d_in, const int* in_sizes, int n_in,
                              void* d_out, int out_size)
{
    const float* x  = (const float*)d_in[0];
    const float* WQ = (const float*)d_in[1];
    const float* WK = (const float*)d_in[2];
    const float* WV = (const float*)d_in[3];
    const float* WO = (const float*)d_in[4];
    float* out = (float*)d_out;

    (void)in_sizes; (void)n_in; (void)out_size;

    cudaFuncSetAttribute(gemm_kernel<0>,
        cudaFuncAttributeMaxDynamicSharedMemorySize, GEMM_SMEM);
    cudaFuncSetAttribute(gemm_kernel<1>,
        cudaFuncAttributeMaxDynamicSharedMemorySize, GEMM_SMEM);
    cudaFuncSetAttribute(attn_kernel,
        cudaFuncAttributeMaxDynamicSharedMemorySize, ATTN_SMEM);

    split_x_kernel<<<M_ * D_ / 8 / 256, 256>>>(x);
    split_wqkv_kernel<<<3 * D_ * D_ / 8 / 256, 256>>>(WQ, WK, WV);
    split_wo_kernel<<<D_ * D_ / 8 / 256, 256>>>(WO);

    gemm_kernel<0><<<dim3(D_ / 128, M_ / 128, 3), 256, GEMM_SMEM>>>(nullptr);
    attn_kernel<<<dim3(S_ / 128, BH_), 256, ATTN_SMEM>>>();
    gemm_kernel<1><<<dim3(D_ / 128, M_ / 128), 256, GEMM_SMEM>>>(out);
}

// round 14
// speedup vs baseline: 8.8591x; 1.2715x over previous
#include <cuda_runtime.h>
#include <cuda_fp16.h>
#include <cstdint>

#define B_  4
#define S_  2048
#define D_  1024
#define H_  16
#define DK_ 64
#define M_  (B_*S_)     // 8192
#define BH_ (B_*H_)     // 64

// fp16 operands
__device__ __half g_Xh2[M_*D_], g_Xl2[M_*D_];   // X split (22-bit) — only split left
__device__ __half g_Wf[3*D_*D_];                 // W qkv single, [z][k][n]
__device__ __half g_Qf[BH_*S_*DK_];              // Q single (scale folded)
__device__ __half g_Kf[BH_*S_*DK_];              // K single
__device__ __half g_Vf[BH_*S_*DK_];              // V single
__device__ __half g_Of[BH_*S_*DK_];              // O single
__device__ __half g_WOf[D_*D_];                  // WO single

// ---------------------------------------------------------------------------
// helpers
// ---------------------------------------------------------------------------
__device__ __forceinline__ unsigned f16pack(float x, float y) {
    __half2 t = __floats2half2_rn(x, y);
    return *reinterpret_cast<unsigned*>(&t);
}
__device__ __forceinline__ void split_f16(float x, float y, unsigned& h, unsigned& l) {
    __half2 t = __floats2half2_rn(x, y);
    float2 b = __half22float2(t);
    h = *reinterpret_cast<unsigned*>(&t);
    __half2 r = __floats2half2_rn(x - b.x, y - b.y);
    l = *reinterpret_cast<unsigned*>(&r);
}
__device__ __forceinline__ unsigned sma(const void* p) {
    return (unsigned)__cvta_generic_to_shared(p);
}
__device__ __forceinline__ void mma_f16(float* c, const unsigned* a, unsigned b0, unsigned b1) {
    asm("mma.sync.aligned.m16n8k16.row.col.f32.f16.f16.f32 "
        "{%0,%1,%2,%3}, {%4,%5,%6,%7}, {%8,%9}, {%0,%1,%2,%3};"
        : "+f"(c[0]), "+f"(c[1]), "+f"(c[2]), "+f"(c[3])
        : "r"(a[0]), "r"(a[1]), "r"(a[2]), "r"(a[3]), "r"(b0), "r"(b1));
}
__device__ __forceinline__ void ldsm_x4(unsigned* r, unsigned a) {
    asm volatile("ldmatrix.sync.aligned.m8n8.x4.shared.b16 {%0,%1,%2,%3}, [%4];"
                 : "=r"(r[0]), "=r"(r[1]), "=r"(r[2]), "=r"(r[3]) : "r"(a));
}
__device__ __forceinline__ void ldsm_x4t(unsigned* r, unsigned a) {
    asm volatile("ldmatrix.sync.aligned.m8n8.x4.trans.shared.b16 {%0,%1,%2,%3}, [%4];"
                 : "=r"(r[0]), "=r"(r[1]), "=r"(r[2]), "=r"(r[3]) : "r"(a));
}
#define CP16(dst, src) \
    asm volatile("cp.async.cg.shared.global [%0], [%1], 16;" :: "r"(dst), "l"(src) : "memory")
#define CPCOMMIT() asm volatile("cp.async.commit_group;" ::: "memory")
#define CPWAIT1()  asm volatile("cp.async.wait_group 1;" ::: "memory")
#define CPWAIT0()  asm volatile("cp.async.wait_group 0;" ::: "memory")

// ---------------------------------------------------------------------------
// Split kernels
// ---------------------------------------------------------------------------
__global__ __launch_bounds__(256) void split_x_kernel(const float* __restrict__ src) {
    size_t i = (size_t)blockIdx.x * 256 + threadIdx.x;
    float4 v0 = *(const float4*)(src + i * 8);
    float4 v1 = *(const float4*)(src + i * 8 + 4);
    unsigned h0,l0,h1,l1,h2,l2,h3,l3;
    split_f16(v0.x, v0.y, h0, l0); split_f16(v0.z, v0.w, h1, l1);
    split_f16(v1.x, v1.y, h2, l2); split_f16(v1.z, v1.w, h3, l3);
    *(uint4*)(g_Xh2 + i * 8) = make_uint4(h0, h1, h2, h3);
    *(uint4*)(g_Xl2 + i * 8) = make_uint4(l0, l1, l2, l3);
}
// W[h][d][dk] (x3) -> fp16 single [z][k=d][n=h*64+dk]
__global__ __launch_bounds__(256) void split_wqkv_kernel(
    const float* __restrict__ WQ, const float* __restrict__ WK, const float* __restrict__ WV)
{
    unsigned i = blockIdx.x * 256 + threadIdx.x;
    int o8 = (i & 7) * 8;
    int d  = (i >> 3) & 1023;
    int h  = (i >> 13) & 15;
    int z  = i >> 17;
    const float* src = ((z == 0) ? WQ : (z == 1) ? WK : WV) + ((size_t)h * D_ + d) * DK_ + o8;
    float4 v0 = *(const float4*)(src);
    float4 v1 = *(const float4*)(src + 4);
    size_t dst = (size_t)z * D_ * D_ + (size_t)d * D_ + h * 64 + o8;
    *(uint4*)(g_Wf + dst) = make_uint4(
        f16pack(v0.x, v0.y), f16pack(v0.z, v0.w),
        f16pack(v1.x, v1.y), f16pack(v1.z, v1.w));
}
__global__ __launch_bounds__(256) void split_wo_kernel(const float* __restrict__ src) {
    size_t i = (size_t)blockIdx.x * 256 + threadIdx.x;
    float4 v0 = *(const float4*)(src + i * 8);
    float4 v1 = *(const float4*)(src + i * 8 + 4);
    *(uint4*)(g_WOf + i * 8) = make_uint4(
        f16pack(v0.x, v0.y), f16pack(v0.z, v0.w),
        f16pack(v1.x, v1.y), f16pack(v1.z, v1.w));
}

// ---------------------------------------------------------------------------
// GEMM: 128x128 tile, 8 warps 4m x 2n, BK=32, cp.async double-buffered.
// MODE 0 = qkv: A split (X hi/lo, 2-term), B = g_Wf[z]; epilogue -> Q/K/V fp16
// MODE 1 = out: A single (g_Of, 1-term),  B = g_WOf;   epilogue -> fp32
// ---------------------------------------------------------------------------
#define AS_LD 40
#define BS_LD 136
#define A_SPLIT 5120                   // 128*40 elems
#define GB_STAGE 4352                  // 32*136 elems

template<int MODE>
__global__ __launch_bounds__(256, 2) void gemm_kernel(float* __restrict__ Out) {
    constexpr int A_ARRS  = (MODE == 0) ? 2 : 1;
    constexpr int A_STAGE = A_ARRS * A_SPLIT;
    constexpr int GB_OFF  = 2 * A_STAGE;

    extern __shared__ __align__(16) char smg[];
    const unsigned sb = sma(smg);
    const int z = (MODE == 0) ? blockIdx.z : 0;
    const __half* Bsrc = (MODE == 0) ? g_Wf + (size_t)z * D_ * D_ : g_WOf;

    const int tid = threadIdx.x, wid = tid >> 5, lane = tid & 31;
    const int wm = wid & 3, wn = wid >> 2;
    const int m0 = blockIdx.y * 128, n0 = blockIdx.x * 128;

    float oc[2][8][4];
#pragma unroll
    for (int a = 0; a < 2; a++)
#pragma unroll
        for (int b = 0; b < 8; b++)
#pragma unroll
            for (int c = 0; c < 4; c++) oc[a][b][c] = 0.f;

    auto stage = [&](int k0, int st) {
#pragma unroll
        for (int u = 0; u < 2 * A_ARRS; u++) {    // A: 128x32 per array
            int sp = u >> 1, rem = tid + (u & 1) * 256;
            int row = rem >> 2, ch = (rem & 3) * 8;
            const __half* src;
            if (MODE == 0) {
                src = (sp ? g_Xl2 : g_Xh2) + (size_t)(m0 + row) * D_ + k0 + ch;
            } else {
                int m = m0 + row, b = m >> 11, s = m & (S_ - 1);
                src = g_Of + ((size_t)(b * H_ + (k0 >> 6)) * S_ + s) * DK_ + (k0 & 63) + ch;
            }
            CP16(sb + (st * A_STAGE + sp * A_SPLIT + row * AS_LD + ch) * 2, src);
        }
#pragma unroll
        for (int u = 0; u < 2; u++) {             // B single: 32x128
            int rem = tid + u * 256;
            int row = rem >> 4, ch = (rem & 15) * 8;
            const __half* src = Bsrc + (size_t)(k0 + row) * D_ + n0 + ch;
            CP16(sb + (GB_OFF + st * GB_STAGE + row * BS_LD + ch) * 2, src);
        }
    };

    stage(0, 0); CPCOMMIT();

    const int arow = lane & 15, acol = (lane >> 4) * 8;
    const int brow = lane & 15, bcol = (lane & 16) >> 1;

    int st = 0;
    for (int k0 = 0; k0 < D_; k0 += 32) {
        if (k0 + 32 < D_) { stage(k0 + 32, st ^ 1); CPCOMMIT(); CPWAIT1(); }
        else CPWAIT0();
        __syncthreads();
#pragma unroll
        for (int h = 0; h < 2; h++) {
            unsigned ah[2][4], al[2][4];
#pragma unroll
            for (int mi = 0; mi < 2; mi++) {
                unsigned ao = sb + (st * A_STAGE + (wm * 32 + mi * 16 + arow) * AS_LD
                                    + acol + h * 16) * 2;
                ldsm_x4(ah[mi], ao);
                if (MODE == 0) ldsm_x4(al[mi], ao + A_SPLIT * 2);
            }
#pragma unroll
            for (int p = 0; p < 4; p++) {
                unsigned bo = sb + (GB_OFF + st * GB_STAGE + (h * 16 + brow) * BS_LD
                                    + wn * 64 + p * 16 + bcol) * 2;
                unsigned bf[4];
                ldsm_x4t(bf, bo);
#pragma unroll
                for (int mi = 0; mi < 2; mi++) {
                    mma_f16(oc[mi][2*p],   ah[mi], bf[0], bf[1]);
                    mma_f16(oc[mi][2*p+1], ah[mi], bf[2], bf[3]);
                    if (MODE == 0) {
                        mma_f16(oc[mi][2*p],   al[mi], bf[0], bf[1]);
                        mma_f16(oc[mi][2*p+1], al[mi], bf[2], bf[3]);
                    }
                }
            }
        }
        __syncthreads();
        st ^= 1;
    }

    const int g = lane >> 2, t = lane & 3;
#pragma unroll
    for (int mi = 0; mi < 2; mi++)
#pragma unroll
        for (int nt = 0; nt < 8; nt++) {
            int n = n0 + wn * 64 + nt * 8 + 2 * t;
            int m = m0 + wm * 32 + mi * 16 + g;
            if (MODE == 0) {
                int hh = n >> 6, d = n & 63;
                int b = m >> 11, s = m & (S_ - 1);
                size_t idx = ((size_t)(b * H_ + hh) * S_ + s) * DK_ + d;
                const float scale = (z == 0) ? 0.125f : 1.0f;
                __half* Dst = (z == 0) ? g_Qf : (z == 1) ? g_Kf : g_Vf;
                *(unsigned*)&Dst[idx] =
                    f16pack(oc[mi][nt][0] * scale, oc[mi][nt][1] * scale);
                *(unsigned*)&Dst[idx + 8 * DK_] =
                    f16pack(oc[mi][nt][2] * scale, oc[mi][nt][3] * scale);
            } else {
                *(float2*)&Out[(size_t)m * D_ + n] =
                    make_float2(oc[mi][nt][0], oc[mi][nt][1]);
                *(float2*)&Out[(size_t)(m + 8) * D_ + n] =
                    make_float2(oc[mi][nt][2], oc[mi][nt][3]);
            }
        }
}
#define GEMM_SMEM0 ((2 * 2 * A_SPLIT + 2 * GB_STAGE) * 2)   // 58368 B
#define GEMM_SMEM1 ((2 * 1 * A_SPLIT + 2 * GB_STAGE) * 2)   // 37888 B

// ---------------------------------------------------------------------------
// Flash attention: scores 1 MMA (Q single x K single), PV 1 MMA.
// ---------------------------------------------------------------------------
#define KV_LD 72
#define KV_ARR_B  (64 * KV_LD * 2)
#define KV_STAGE_B (2 * KV_ARR_B)
#define ATTN_SMEM (2 * KV_STAGE_B)        // 36864 B

__global__ __launch_bounds__(256) void attn_kernel() {
    extern __shared__ __align__(16) char smg[];
    __half* smh = (__half*)smg;
    const unsigned sb = sma(smg);
    const int tid = threadIdx.x, wid = tid >> 5, lane = tid & 31;
    const int g = lane >> 2, t = lane & 3;
    const int bh = blockIdx.y, q0 = blockIdx.x * 128;
    const size_t base = (size_t)bh * S_ * DK_;

    // hoist Q fragments (single array)
    unsigned qh[4][4];
    {
        for (int i = tid; i < 1024; i += 256) {
            int row = i >> 3, c8 = (i & 7) * 8;
            *(uint4*)&smh[row * KV_LD + c8] =
                *(const uint4*)&g_Qf[base + (size_t)(q0 + row) * DK_ + c8];
        }
        __syncthreads();
        unsigned ad = sb + ((wid * 16 + (lane & 15)) * KV_LD + (lane >> 4) * 8) * 2;
#pragma unroll
        for (int kt = 0; kt < 4; kt++)
            ldsm_x4(qh[kt], ad + kt * 32);
        __syncthreads();
    }

    float oc[8][4];
#pragma unroll
    for (int i = 0; i < 8; i++)
#pragma unroll
        for (int j = 0; j < 4; j++) oc[i][j] = 0.f;
    float m0r = -1e30f, m1r = -1e30f, l0r = 0.f, l1r = 0.f;

    const unsigned kb = (((lane & 7) + ((lane & 16) >> 1)) * KV_LD + (lane & 8)) * 2;
    const unsigned vb = ((lane & 15) * KV_LD + ((lane & 16) >> 1)) * 2;

    auto stage = [&](int kv0, int st) {
#pragma unroll
        for (int u = 0; u < 4; u++) {
            int arr = u >> 1, rem = tid + (u & 1) * 256;
            int row = rem >> 3, ch = (rem & 7) * 8;
            const __half* s = (arr == 0 ? g_Kf : g_Vf)
                + base + (size_t)(kv0 + row) * DK_ + ch;
            CP16(sb + st * KV_STAGE_B + arr * KV_ARR_B + (row * KV_LD + ch) * 2, s);
        }
    };

    stage(0, 0); CPCOMMIT();

    int st = 0;
    for (int kv0 = 0; kv0 < S_; kv0 += 64) {
        if (kv0 + 64 < S_) { stage(kv0 + 64, st ^ 1); CPCOMMIT(); CPWAIT1(); }
        else CPWAIT0();
        __syncthreads();

        const unsigned kK = sb + st * KV_STAGE_B + kb;
        const unsigned vV = sb + st * KV_STAGE_B + KV_ARR_B + vb;

        // ---- scores: 1 MMA per (p,kt,half) ----
        float sc[8][4];
#pragma unroll
        for (int i = 0; i < 8; i++)
#pragma unroll
            for (int j = 0; j < 4; j++) sc[i][j] = 0.f;
#pragma unroll
        for (int p = 0; p < 4; p++) {
#pragma unroll
            for (int kt = 0; kt < 4; kt++) {
                unsigned off = (unsigned)(p * 16 * KV_LD + kt * 16) * 2;
                unsigned kf[4];
                ldsm_x4(kf, kK + off);
                mma_f16(sc[2*p],   qh[kt], kf[0], kf[1]);
                mma_f16(sc[2*p+1], qh[kt], kf[2], kf[3]);
            }
        }

        // ---- online softmax (rows g, g+8) ----
        float mx0 = sc[0][0], mx1 = sc[0][2];
#pragma unroll
        for (int nt = 0; nt < 8; nt++) {
            mx0 = fmaxf(mx0, fmaxf(sc[nt][0], sc[nt][1]));
            mx1 = fmaxf(mx1, fmaxf(sc[nt][2], sc[nt][3]));
        }
        mx0 = fmaxf(mx0, __shfl_xor_sync(0xffffffffu, mx0, 1));
        mx0 = fmaxf(mx0, __shfl_xor_sync(0xffffffffu, mx0, 2));
        mx1 = fmaxf(mx1, __shfl_xor_sync(0xffffffffu, mx1, 1));
        mx1 = fmaxf(mx1, __shfl_xor_sync(0xffffffffu, mx1, 2));
        float mn0 = fmaxf(m0r, mx0), mn1 = fmaxf(m1r, mx1);
        float cr0 = __expf(m0r - mn0), cr1 = __expf(m1r - mn1);
        m0r = mn0; m1r = mn1;
        float s0 = 0.f, s1 = 0.f;
#pragma unroll
        for (int nt = 0; nt < 8; nt++) {
            sc[nt][0] = __expf(sc[nt][0] - mn0);
            sc[nt][1] = __expf(sc[nt][1] - mn0);
            sc[nt][2] = __expf(sc[nt][2] - mn1);
            sc[nt][3] = __expf(sc[nt][3] - mn1);
            s0 += sc[nt][0] + sc[nt][1];
            s1 += sc[nt][2] + sc[nt][3];
        }
        s0 += __shfl_xor_sync(0xffffffffu, s0, 1);
        s0 += __shfl_xor_sync(0xffffffffu, s0, 2);
        s1 += __shfl_xor_sync(0xffffffffu, s1, 1);
        s1 += __shfl_xor_sync(0xffffffffu, s1, 2);
        l0r = l0r * cr0 + s0;
        l1r = l1r * cr1 + s1;
#pragma unroll
        for (int nt = 0; nt < 8; nt++) {
            oc[nt][0] *= cr0; oc[nt][1] *= cr0;
            oc[nt][2] *= cr1; oc[nt][3] *= cr1;
        }

        // ---- pack P single fp16 ----
        unsigned pa[4][4];
#pragma unroll
        for (int kt = 0; kt < 4; kt++) {
            int j0 = 2 * kt, j1 = 2 * kt + 1;
            pa[kt][0] = f16pack(sc[j0][0], sc[j0][1]);
            pa[kt][1] = f16pack(sc[j0][2], sc[j0][3]);
            pa[kt][2] = f16pack(sc[j1][0], sc[j1][1]);
            pa[kt][3] = f16pack(sc[j1][2], sc[j1][3]);
        }

        // ---- PV: 1 MMA ----
#pragma unroll
        for (int p = 0; p < 4; p++) {
#pragma unroll
            for (int kt = 0; kt < 4; kt++) {
                unsigned off = (unsigned)(kt * 16 * KV_LD + p * 16) * 2;
                unsigned vf[4];
                ldsm_x4t(vf, vV + off);
                mma_f16(oc[2*p],   pa[kt], vf[0], vf[1]);
                mma_f16(oc[2*p+1], pa[kt], vf[2], vf[3]);
            }
        }
        __syncthreads();
        st ^= 1;
    }

    // epilogue: normalize, store O single fp16
    const float i0 = 1.f / l0r, i1 = 1.f / l1r;
    const int r = q0 + wid * 16 + g;
#pragma unroll
    for (int nt = 0; nt < 8; nt++) {
        int d = nt * 8 + 2 * t;
        *(unsigned*)&g_Of[base + (size_t)r * DK_ + d] =
            f16pack(oc[nt][0] * i0, oc[nt][1] * i0);
        *(unsigned*)&g_Of[base + (size_t)(r + 8) * DK_ + d] =
            f16pack(oc[nt][2] * i1, oc[nt][3] * i1);
    }
}

// ---------------------------------------------------------------------------
extern "C" void kernel_launch(void* const* d_in, const int* in_sizes, int n_in,
                              void* d_out, int out_size)
{
    const float* x  = (const float*)d_in[0];
    const float* WQ = (const float*)d_in[1];
    const float* WK = (const float*)d_in[2];
    const float* WV = (const float*)d_in[3];
    const float* WO = (const float*)d_in[4];
    float* out = (float*)d_out;

    (void)in_sizes; (void)n_in; (void)out_size;

    cudaFuncSetAttribute(gemm_kernel<0>,
        cudaFuncAttributeMaxDynamicSharedMemorySize, GEMM_SMEM0);
    cudaFuncSetAttribute(gemm_kernel<1>,
        cudaFuncAttributeMaxDynamicSharedMemorySize, GEMM_SMEM1);
    cudaFuncSetAttribute(attn_kernel,
        cudaFuncAttributeMaxDynamicSharedMemorySize, ATTN_SMEM);

    split_x_kernel<<<M_ * D_ / 8 / 256, 256>>>(x);
    split_wqkv_kernel<<<3 * D_ * D_ / 8 / 256, 256>>>(WQ, WK, WV);
    split_wo_kernel<<<D_ * D_ / 8 / 256, 256>>>(WO);

    gemm_kernel<0><<<dim3(D_ / 128, M_ / 128, 3), 256, GEMM_SMEM0>>>(nullptr);
    attn_kernel<<<dim3(S_ / 128, BH_), 256, ATTN_SMEM>>>();
    gemm_kernel<1><<<dim3(D_ / 128, M_ / 128), 256, GEMM_SMEM1>>>(out);
}

// round 16
// speedup vs baseline: 11.2440x; 1.2692x over previous
#include <cuda_runtime.h>
#include <cuda_fp16.h>
#include <cstdint>

#define B_  4
#define S_  2048
#define D_  1024
#define H_  16
#define DK_ 64
#define M_  (B_*S_)     // 8192
#define BH_ (B_*H_)     // 64

// fp16 operands — all single precision-level (error budget fully allocated)
__device__ __half g_Xf[M_*D_];                   // X single
__device__ __half g_Wf[3*D_*D_];                 // W qkv, [z][k][n]
__device__ __half g_Qf[BH_*S_*DK_];              // Q (scale folded)
__device__ __half g_Kf[BH_*S_*DK_];
__device__ __half g_Vf[BH_*S_*DK_];
__device__ __half g_Of[BH_*S_*DK_];
__device__ __half g_WOf[D_*D_];

// ---------------------------------------------------------------------------
// helpers
// ---------------------------------------------------------------------------
__device__ __forceinline__ unsigned f16pack(float x, float y) {
    __half2 t = __floats2half2_rn(x, y);
    return *reinterpret_cast<unsigned*>(&t);
}
__device__ __forceinline__ unsigned sma(const void* p) {
    return (unsigned)__cvta_generic_to_shared(p);
}
__device__ __forceinline__ void mma_f16(float* c, const unsigned* a, unsigned b0, unsigned b1) {
    asm("mma.sync.aligned.m16n8k16.row.col.f32.f16.f16.f32 "
        "{%0,%1,%2,%3}, {%4,%5,%6,%7}, {%8,%9}, {%0,%1,%2,%3};"
        : "+f"(c[0]), "+f"(c[1]), "+f"(c[2]), "+f"(c[3])
        : "r"(a[0]), "r"(a[1]), "r"(a[2]), "r"(a[3]), "r"(b0), "r"(b1));
}
__device__ __forceinline__ void ldsm_x4(unsigned* r, unsigned a) {
    asm volatile("ldmatrix.sync.aligned.m8n8.x4.shared.b16 {%0,%1,%2,%3}, [%4];"
                 : "=r"(r[0]), "=r"(r[1]), "=r"(r[2]), "=r"(r[3]) : "r"(a));
}
__device__ __forceinline__ void ldsm_x4t(unsigned* r, unsigned a) {
    asm volatile("ldmatrix.sync.aligned.m8n8.x4.trans.shared.b16 {%0,%1,%2,%3}, [%4];"
                 : "=r"(r[0]), "=r"(r[1]), "=r"(r[2]), "=r"(r[3]) : "r"(a));
}
#define CP16(dst, src) \
    asm volatile("cp.async.cg.shared.global [%0], [%1], 16;" :: "r"(dst), "l"(src) : "memory")
#define CPCOMMIT() asm volatile("cp.async.commit_group;" ::: "memory")
#define CPWAIT1()  asm volatile("cp.async.wait_group 1;" ::: "memory")
#define CPWAIT0()  asm volatile("cp.async.wait_group 0;" ::: "memory")

// ---------------------------------------------------------------------------
// Convert kernels (fp32 -> fp16)
// ---------------------------------------------------------------------------
__global__ __launch_bounds__(256) void conv_x_kernel(const float* __restrict__ src) {
    size_t i = (size_t)blockIdx.x * 256 + threadIdx.x;
    float4 v0 = *(const float4*)(src + i * 8);
    float4 v1 = *(const float4*)(src + i * 8 + 4);
    *(uint4*)(g_Xf + i * 8) = make_uint4(
        f16pack(v0.x, v0.y), f16pack(v0.z, v0.w),
        f16pack(v1.x, v1.y), f16pack(v1.z, v1.w));
}
// W[h][d][dk] (x3) -> [z][k=d][n=h*64+dk]
__global__ __launch_bounds__(256) void conv_wqkv_kernel(
    const float* __restrict__ WQ, const float* __restrict__ WK, const float* __restrict__ WV)
{
    unsigned i = blockIdx.x * 256 + threadIdx.x;
    int o8 = (i & 7) * 8;
    int d  = (i >> 3) & 1023;
    int h  = (i >> 13) & 15;
    int z  = i >> 17;
    const float* src = ((z == 0) ? WQ : (z == 1) ? WK : WV) + ((size_t)h * D_ + d) * DK_ + o8;
    float4 v0 = *(const float4*)(src);
    float4 v1 = *(const float4*)(src + 4);
    size_t dst = (size_t)z * D_ * D_ + (size_t)d * D_ + h * 64 + o8;
    *(uint4*)(g_Wf + dst) = make_uint4(
        f16pack(v0.x, v0.y), f16pack(v0.z, v0.w),
        f16pack(v1.x, v1.y), f16pack(v1.z, v1.w));
}
__global__ __launch_bounds__(256) void conv_wo_kernel(const float* __restrict__ src) {
    size_t i = (size_t)blockIdx.x * 256 + threadIdx.x;
    float4 v0 = *(const float4*)(src + i * 8);
    float4 v1 = *(const float4*)(src + i * 8 + 4);
    *(uint4*)(g_WOf + i * 8) = make_uint4(
        f16pack(v0.x, v0.y), f16pack(v0.z, v0.w),
        f16pack(v1.x, v1.y), f16pack(v1.z, v1.w));
}

// ---------------------------------------------------------------------------
// GEMM: 128x128 tile, 8 warps 4m x 2n, BK=32, 1-term fp16, cp.async DB.
// MODE 0 = qkv: A = g_Xf, B = g_Wf[z]; epilogue -> Q/K/V fp16
// MODE 1 = out: A = g_Of, B = g_WOf;   epilogue -> fp32
// ---------------------------------------------------------------------------
#define AS_LD 40
#define BS_LD 136
#define A_STAGE 5120                   // 128*40 elems
#define GB_OFF  (2 * A_STAGE)
#define GB_STAGE 4352                  // 32*136 elems
#define GEMM_SMEM ((2 * A_STAGE + 2 * GB_STAGE) * 2)   // 37888 B

template<int MODE>
__global__ __launch_bounds__(256, 2) void gemm_kernel(float* __restrict__ Out) {
    extern __shared__ __align__(16) char smg[];
    const unsigned sb = sma(smg);
    const int z = (MODE == 0) ? blockIdx.z : 0;
    const __half* Bsrc = (MODE == 0) ? g_Wf + (size_t)z * D_ * D_ : g_WOf;

    const int tid = threadIdx.x, wid = tid >> 5, lane = tid & 31;
    const int wm = wid & 3, wn = wid >> 2;
    const int m0 = blockIdx.y * 128, n0 = blockIdx.x * 128;

    float oc[2][8][4];
#pragma unroll
    for (int a = 0; a < 2; a++)
#pragma unroll
        for (int b = 0; b < 8; b++)
#pragma unroll
            for (int c = 0; c < 4; c++) oc[a][b][c] = 0.f;

    auto stage = [&](int k0, int st) {
#pragma unroll
        for (int u = 0; u < 2; u++) {             // A: 128x32
            int rem = tid + u * 256;
            int row = rem >> 2, ch = (rem & 3) * 8;
            const __half* src;
            if (MODE == 0) {
                src = g_Xf + (size_t)(m0 + row) * D_ + k0 + ch;
            } else {
                int m = m0 + row, b = m >> 11, s = m & (S_ - 1);
                src = g_Of + ((size_t)(b * H_ + (k0 >> 6)) * S_ + s) * DK_ + (k0 & 63) + ch;
            }
            CP16(sb + (st * A_STAGE + row * AS_LD + ch) * 2, src);
        }
#pragma unroll
        for (int u = 0; u < 2; u++) {             // B: 32x128
            int rem = tid + u * 256;
            int row = rem >> 4, ch = (rem & 15) * 8;
            const __half* src = Bsrc + (size_t)(k0 + row) * D_ + n0 + ch;
            CP16(sb + (GB_OFF + st * GB_STAGE + row * BS_LD + ch) * 2, src);
        }
    };

    stage(0, 0); CPCOMMIT();

    const int arow = lane & 15, acol = (lane >> 4) * 8;
    const int brow = lane & 15, bcol = (lane & 16) >> 1;

    int st = 0;
    for (int k0 = 0; k0 < D_; k0 += 32) {
        if (k0 + 32 < D_) { stage(k0 + 32, st ^ 1); CPCOMMIT(); CPWAIT1(); }
        else CPWAIT0();
        __syncthreads();
#pragma unroll
        for (int h = 0; h < 2; h++) {
            unsigned ah[2][4];
#pragma unroll
            for (int mi = 0; mi < 2; mi++) {
                unsigned ao = sb + (st * A_STAGE + (wm * 32 + mi * 16 + arow) * AS_LD
                                    + acol + h * 16) * 2;
                ldsm_x4(ah[mi], ao);
            }
#pragma unroll
            for (int p = 0; p < 4; p++) {
                unsigned bo = sb + (GB_OFF + st * GB_STAGE + (h * 16 + brow) * BS_LD
                                    + wn * 64 + p * 16 + bcol) * 2;
                unsigned bf[4];
                ldsm_x4t(bf, bo);
#pragma unroll
                for (int mi = 0; mi < 2; mi++) {
                    mma_f16(oc[mi][2*p],   ah[mi], bf[0], bf[1]);
                    mma_f16(oc[mi][2*p+1], ah[mi], bf[2], bf[3]);
                }
            }
        }
        __syncthreads();
        st ^= 1;
    }

    const int g = lane >> 2, t = lane & 3;
#pragma unroll
    for (int mi = 0; mi < 2; mi++)
#pragma unroll
        for (int nt = 0; nt < 8; nt++) {
            int n = n0 + wn * 64 + nt * 8 + 2 * t;
            int m = m0 + wm * 32 + mi * 16 + g;
            if (MODE == 0) {
                int hh = n >> 6, d = n & 63;
                int b = m >> 11, s = m & (S_ - 1);
                size_t idx = ((size_t)(b * H_ + hh) * S_ + s) * DK_ + d;
                const float scale = (z == 0) ? 0.125f : 1.0f;
                __half* Dst = (z == 0) ? g_Qf : (z == 1) ? g_Kf : g_Vf;
                *(unsigned*)&Dst[idx] =
                    f16pack(oc[mi][nt][0] * scale, oc[mi][nt][1] * scale);
                *(unsigned*)&Dst[idx + 8 * DK_] =
                    f16pack(oc[mi][nt][2] * scale, oc[mi][nt][3] * scale);
            } else {
                *(float2*)&Out[(size_t)m * D_ + n] =
                    make_float2(oc[mi][nt][0], oc[mi][nt][1]);
                *(float2*)&Out[(size_t)(m + 8) * D_ + n] =
                    make_float2(oc[mi][nt][2], oc[mi][nt][3]);
            }
        }
}

// ---------------------------------------------------------------------------
// Flash attention: scores 1 MMA (Q x K), PV 1 MMA. cp.async DB KV.
// ---------------------------------------------------------------------------
#define KV_LD 72
#define KV_ARR_B  (64 * KV_LD * 2)
#define KV_STAGE_B (2 * KV_ARR_B)
#define ATTN_SMEM (2 * KV_STAGE_B)        // 36864 B

__global__ __launch_bounds__(256) void attn_kernel() {
    extern __shared__ __align__(16) char smg[];
    __half* smh = (__half*)smg;
    const unsigned sb = sma(smg);
    const int tid = threadIdx.x, wid = tid >> 5, lane = tid & 31;
    const int g = lane >> 2, t = lane & 3;
    const int bh = blockIdx.y, q0 = blockIdx.x * 128;
    const size_t base = (size_t)bh * S_ * DK_;

    unsigned qh[4][4];
    {
        for (int i = tid; i < 1024; i += 256) {
            int row = i >> 3, c8 = (i & 7) * 8;
            *(uint4*)&smh[row * KV_LD + c8] =
                *(const uint4*)&g_Qf[base + (size_t)(q0 + row) * DK_ + c8];
        }
        __syncthreads();
        unsigned ad = sb + ((wid * 16 + (lane & 15)) * KV_LD + (lane >> 4) * 8) * 2;
#pragma unroll
        for (int kt = 0; kt < 4; kt++)
            ldsm_x4(qh[kt], ad + kt * 32);
        __syncthreads();
    }

    float oc[8][4];
#pragma unroll
    for (int i = 0; i < 8; i++)
#pragma unroll
        for (int j = 0; j < 4; j++) oc[i][j] = 0.f;
    float m0r = -1e30f, m1r = -1e30f, l0r = 0.f, l1r = 0.f;

    const unsigned kb = (((lane & 7) + ((lane & 16) >> 1)) * KV_LD + (lane & 8)) * 2;
    const unsigned vb = ((lane & 15) * KV_LD + ((lane & 16) >> 1)) * 2;

    auto stage = [&](int kv0, int st) {
#pragma unroll
        for (int u = 0; u < 4; u++) {
            int arr = u >> 1, rem = tid + (u & 1) * 256;
            int row = rem >> 3, ch = (rem & 7) * 8;
            const __half* s = (arr == 0 ? g_Kf : g_Vf)
                + base + (size_t)(kv0 + row) * DK_ + ch;
            CP16(sb + st * KV_STAGE_B + arr * KV_ARR_B + (row * KV_LD + ch) * 2, s);
        }
    };

    stage(0, 0); CPCOMMIT();

    int st = 0;
    for (int kv0 = 0; kv0 < S_; kv0 += 64) {
        if (kv0 + 64 < S_) { stage(kv0 + 64, st ^ 1); CPCOMMIT(); CPWAIT1(); }
        else CPWAIT0();
        __syncthreads();

        const unsigned kK = sb + st * KV_STAGE_B + kb;
        const unsigned vV = sb + st * KV_STAGE_B + KV_ARR_B + vb;

        float sc[8][4];
#pragma unroll
        for (int i = 0; i < 8; i++)
#pragma unroll
            for (int j = 0; j < 4; j++) sc[i][j] = 0.f;
#pragma unroll
        for (int p = 0; p < 4; p++) {
#pragma unroll
            for (int kt = 0; kt < 4; kt++) {
                unsigned off = (unsigned)(p * 16 * KV_LD + kt * 16) * 2;
                unsigned kf[4];
                ldsm_x4(kf, kK + off);
                mma_f16(sc[2*p],   qh[kt], kf[0], kf[1]);
                mma_f16(sc[2*p+1], qh[kt], kf[2], kf[3]);
            }
        }

        float mx0 = sc[0][0], mx1 = sc[0][2];
#pragma unroll
        for (int nt = 0; nt < 8; nt++) {
            mx0 = fmaxf(mx0, fmaxf(sc[nt][0], sc[nt][1]));
            mx1 = fmaxf(mx1, fmaxf(sc[nt][2], sc[nt][3]));
        }
        mx0 = fmaxf(mx0, __shfl_xor_sync(0xffffffffu, mx0, 1));
        mx0 = fmaxf(mx0, __shfl_xor_sync(0xffffffffu, mx0, 2));
        mx1 = fmaxf(mx1, __shfl_xor_sync(0xffffffffu, mx1, 1));
        mx1 = fmaxf(mx1, __shfl_xor_sync(0xffffffffu, mx1, 2));
        float mn0 = fmaxf(m0r, mx0), mn1 = fmaxf(m1r, mx1);
        float cr0 = __expf(m0r - mn0), cr1 = __expf(m1r - mn1);
        m0r = mn0; m1r = mn1;
        float s0 = 0.f, s1 = 0.f;
#pragma unroll
        for (int nt = 0; nt < 8; nt++) {
            sc[nt][0] = __expf(sc[nt][0] - mn0);
            sc[nt][1] = __expf(sc[nt][1] - mn0);
            sc[nt][2] = __expf(sc[nt][2] - mn1);
            sc[nt][3] = __expf(sc[nt][3] - mn1);
            s0 += sc[nt][0] + sc[nt][1];
            s1 += sc[nt][2] + sc[nt][3];
        }
        s0 += __shfl_xor_sync(0xffffffffu, s0, 1);
        s0 += __shfl_xor_sync(0xffffffffu, s0, 2);
        s1 += __shfl_xor_sync(0xffffffffu, s1, 1);
        s1 += __shfl_xor_sync(0xffffffffu, s1, 2);
        l0r = l0r * cr0 + s0;
        l1r = l1r * cr1 + s1;
#pragma unroll
        for (int nt = 0; nt < 8; nt++) {
            oc[nt][0] *= cr0; oc[nt][1] *= cr0;
            oc[nt][2] *= cr1; oc[nt][3] *= cr1;
        }

        unsigned pa[4][4];
#pragma unroll
        for (int kt = 0; kt < 4; kt++) {
            int j0 = 2 * kt, j1 = 2 * kt + 1;
            pa[kt][0] = f16pack(sc[j0][0], sc[j0][1]);
            pa[kt][1] = f16pack(sc[j0][2], sc[j0][3]);
            pa[kt][2] = f16pack(sc[j1][0], sc[j1][1]);
            pa[kt][3] = f16pack(sc[j1][2], sc[j1][3]);
        }

#pragma unroll
        for (int p = 0; p < 4; p++) {
#pragma unroll
            for (int kt = 0; kt < 4; kt++) {
                unsigned off = (unsigned)(kt * 16 * KV_LD + p * 16) * 2;
                unsigned vf[4];
                ldsm_x4t(vf, vV + off);
                mma_f16(oc[2*p],   pa[kt], vf[0], vf[1]);
                mma_f16(oc[2*p+1], pa[kt], vf[2], vf[3]);
            }
        }
        __syncthreads();
        st ^= 1;
    }

    const float i0 = 1.f / l0r, i1 = 1.f / l1r;
    const int r = q0 + wid * 16 + g;
#pragma unroll
    for (int nt = 0; nt < 8; nt++) {
        int d = nt * 8 + 2 * t;
        *(unsigned*)&g_Of[base + (size_t)r * DK_ + d] =
            f16pack(oc[nt][0] * i0, oc[nt][1] * i0);
        *(unsigned*)&g_Of[base + (size_t)(r + 8) * DK_ + d] =
            f16pack(oc[nt][2] * i1, oc[nt][3] * i1);
    }
}

// ---------------------------------------------------------------------------
extern "C" void kernel_launch(void* const* d_in, const int* in_sizes, int n_in,
                              void* d_out, int out_size)
{
    const float* x  = (const float*)d_in[0];
    const float* WQ = (const float*)d_in[1];
    const float* WK = (const float*)d_in[2];
    const float* WV = (const float*)d_in[3];
    const float* WO = (const float*)d_in[4];
    float* out = (float*)d_out;

    (void)in_sizes; (void)n_in; (void)out_size;

    cudaFuncSetAttribute(gemm_kernel<0>,
        cudaFuncAttributeMaxDynamicSharedMemorySize, GEMM_SMEM);
    cudaFuncSetAttribute(gemm_kernel<1>,
        cudaFuncAttributeMaxDynamicSharedMemorySize, GEMM_SMEM);
    cudaFuncSetAttribute(attn_kernel,
        cudaFuncAttributeMaxDynamicSharedMemorySize, ATTN_SMEM);

    conv_x_kernel<<<M_ * D_ / 8 / 256, 256>>>(x);
    conv_wqkv_kernel<<<3 * D_ * D_ / 8 / 256, 256>>>(WQ, WK, WV);
    conv_wo_kernel<<<D_ * D_ / 8 / 256, 256>>>(WO);

    gemm_kernel<0><<<dim3(D_ / 128, M_ / 128, 3), 256, GEMM_SMEM>>>(nullptr);
    attn_kernel<<<dim3(S_ / 128, BH_), 256, ATTN_SMEM>>>();
    gemm_kernel<1><<<dim3(D_ / 128, M_ / 128), 256, GEMM_SMEM>>>(out);
}